// round 10
// baseline (speedup 1.0000x reference)
#include <cuda_runtime.h>
#include <cuda_bf16.h>
#include <math.h>

#define BB 8
#define CC 64
#define HEADS 4
#define CH 16
#define HH 256
#define WW 256
#define HW (HH*WW)
#define EPS 1e-12f

typedef unsigned int u32;

// ---------------- static device scratch ----------------
__device__ float g_q [BB*CC*HW];
__device__ float g_k [BB*CC*HW];
__device__ float g_v [BB*CC*HW];
__device__ float g_t0[BB*CC*HW];
__device__ float g_gram[BB*HEADS*CH*CH];
__device__ float g_qn[BB*CC];
__device__ float g_kn[BB*CC];
__device__ __align__(16) u32 g_wbuf [4*9*64*64];  // conv wts [conv][tap][ic][oc] tf32
__device__ __align__(16) u32 g_wqkv[3*64*64];     // qkv  wts [g][ic][oc] tf32

__device__ __forceinline__ u32 to_tf32(float v) {
    u32 t; asm("cvt.rna.tf32.f32 %0, %1;" : "=r"(t) : "f"(v)); return t;
}
__device__ __forceinline__ void mma_tf32(float* d, u32 a0, u32 a1, u32 a2, u32 a3,
                                         u32 b0, u32 b1) {
    asm volatile(
        "mma.sync.aligned.m16n8k8.row.col.f32.tf32.tf32.f32 "
        "{%0,%1,%2,%3}, {%4,%5,%6,%7}, {%8,%9}, {%0,%1,%2,%3};"
        : "+f"(d[0]), "+f"(d[1]), "+f"(d[2]), "+f"(d[3])
        : "r"(a0), "r"(a1), "r"(a2), "r"(a3), "r"(b0), "r"(b1));
}

// ---------------- weight prep + zeroing (tiny, runs first) ------------------
__global__ void k_wprep(const float* __restrict__ w0, const float* __restrict__ w1,
                        const float* __restrict__ w2, const float* __restrict__ w3,
                        const float* __restrict__ qw, const float* __restrict__ kw,
                        const float* __restrict__ vw) {
    int gtid = blockIdx.x*256 + threadIdx.x;     // 16384 threads
    const float* ws[4] = {w0, w1, w2, w3};
#pragma unroll
    for (int c = 0; c < 4; c++) {
        const float* wp = ws[c];
        for (int e = gtid; e < 9*64*64; e += 16384) {
            int tap = e >> 12, r = e & 4095;
            int ic = r >> 6, oc = r & 63;
            g_wbuf[c*36864 + tap*4096 + ic*64 + oc] = to_tf32(wp[oc*576 + ic*9 + tap]);
        }
    }
    const float* qs[3] = {qw, kw, vw};
#pragma unroll
    for (int g = 0; g < 3; g++) {
        for (int e = gtid; e < 4096; e += 16384) {
            int ic = e >> 6, oc = e & 63;
            g_wqkv[g*4096 + ic*64 + oc] = to_tf32(qs[g][oc*64 + ic]);
        }
    }
    if (gtid < BB*HEADS*CH*CH) g_gram[gtid] = 0.f;
    if (gtid < BB*CC) { g_qn[gtid] = 0.f; g_kn[gtid] = 0.f; }
}

// ---------------- q,k,v 1x1 convs via tf32 MMA ------------------------------
// grid (HW/64, BB, 3); block 256 = 8 warps (wm 0..3, wn 0..1); tile 64oc x 64px
__global__ void __launch_bounds__(256) k_qkvmma(
        const float* __restrict__ x, const float* __restrict__ y,
        const float* __restrict__ qb, const float* __restrict__ kb,
        const float* __restrict__ vb) {
    __shared__ __align__(16) u32 sIn[16*72];
    __shared__ __align__(16) u32 sW [16*72];
    int tid = threadIdx.x, lane = tid & 31, wid = tid >> 5;
    int wm = wid & 3, wn = wid >> 2;
    int t4 = lane & 3, g8 = lane >> 2;
    int g = blockIdx.z, b = blockIdx.y;
    int px0 = blockIdx.x*64;
    const float* in  = (g == 0 ? x : y) + (size_t)b*CC*HW + px0;
    const u32* wsrc  = g_wqkv + g*4096;
    const float* bia = g == 0 ? qb : (g == 1 ? kb : vb);
    float* outp = (g == 0 ? g_q : (g == 1 ? g_k : g_v)) + (size_t)b*CC*HW + px0;

    float acc[4][4];
#pragma unroll
    for (int j = 0; j < 4; j++)
#pragma unroll
        for (int r = 0; r < 4; r++) acc[j][r] = 0.f;

    for (int icb = 0; icb < 64; icb += 16) {
        for (int i = tid; i < 1024; i += 256) {
            int ic = i >> 6, p = i & 63;
            sIn[ic*72 + p] = to_tf32(in[(size_t)(icb+ic)*HW + p]);
        }
        for (int i = tid; i < 1024; i += 256) {
            int ic = i >> 6, oc = i & 63;
            sW[ic*72 + oc] = wsrc[(icb+ic)*64 + oc];
        }
        __syncthreads();
#pragma unroll
        for (int ks = 0; ks < 2; ks++) {
            int arow = (ks*8 + t4)*72 + wm*16 + g8;
            u32 a0 = sW[arow], a1 = sW[arow+8], a2 = sW[arow+4*72], a3 = sW[arow+4*72+8];
            int ib = (ks*8 + t4)*72;
#pragma unroll
            for (int j = 0; j < 4; j++) {
                int px = wn*32 + j*8 + g8;
                u32 b0 = sIn[ib + px], b1 = sIn[ib + 4*72 + px];
                mma_tf32(acc[j], a0, a1, a2, a3, b0, b1);
            }
        }
        __syncthreads();
    }
#pragma unroll
    for (int j = 0; j < 4; j++) {
        int p = wn*32 + j*8 + 2*t4;
#pragma unroll
        for (int mh = 0; mh < 2; mh++) {
            int oc = wm*16 + g8 + mh*8;
            float bv = __ldg(&bia[oc]);
            *reinterpret_cast<float2*>(&outp[(size_t)oc*HW + p]) =
                make_float2(acc[j][mh*2+0] + bv, acc[j][mh*2+1] + bv);
        }
    }
}

// ---------------- gram + norms ----------------------------------------------
__global__ void k_gram() {
    __shared__ float qs[16*65];
    __shared__ float ks[16*65];
    int tid = threadIdx.x;
    int c = tid & 15, d = tid >> 4;
    int bh = blockIdx.y, b = bh >> 2, h = bh & 3;
    const float* qp = g_q + ((size_t)b*CC + h*CH)*HW;
    const float* kp = g_k + ((size_t)b*CC + h*CH)*HW;
    float acc = 0.f, nacc = 0.f;
    for (int t = 0; t < 32; t++) {
        int n0 = blockIdx.x*2048 + t*64;
        for (int idx = tid; idx < 1024; idx += 256) {
            int r = idx >> 6, j = idx & 63;
            qs[r*65 + j] = qp[(size_t)r*HW + n0 + j];
            ks[r*65 + j] = kp[(size_t)r*HW + n0 + j];
        }
        __syncthreads();
#pragma unroll 8
        for (int j = 0; j < 64; j++) acc += qs[c*65 + j] * ks[d*65 + j];
        if (d == 0) {
#pragma unroll 8
            for (int j = 0; j < 64; j++) { float v = qs[c*65 + j]; nacc += v*v; }
        } else if (d == 1) {
#pragma unroll 8
            for (int j = 0; j < 64; j++) { float v = ks[c*65 + j]; nacc += v*v; }
        }
        __syncthreads();
    }
    atomicAdd(&g_gram[bh*256 + c*16 + d], acc);
    if (d == 0) atomicAdd(&g_qn[b*CC + h*CH + c], nacc);
    if (d == 1) atomicAdd(&g_kn[b*CC + h*CH + c], nacc);
}

// ---------------- apply with per-block softmax recompute --------------------
__global__ void k_applysm() {
    __shared__ __align__(16) float sa[HEADS*CH*CH];
    int tid = threadIdx.x;
    int b = blockIdx.y;
    if (tid < 64) {
        int h = tid >> 4, c = tid & 15;
        float nq = fmaxf(sqrtf(g_qn[b*CC + h*CH + c]), EPS);
        float l[16], m = -1e30f;
#pragma unroll
        for (int d = 0; d < 16; d++) {
            float nk = fmaxf(sqrtf(g_kn[b*CC + h*CH + d]), EPS);
            l[d] = g_gram[(b*4+h)*256 + c*16 + d] / (nq * nk);
            m = fmaxf(m, l[d]);
        }
        float s = 0.f;
#pragma unroll
        for (int d = 0; d < 16; d++) { l[d] = expf(l[d] - m); s += l[d]; }
        float inv = 1.f / s;
#pragma unroll
        for (int d = 0; d < 16; d++) sa[h*256 + c*16 + d] = l[d] * inv;
    }
    __syncthreads();
    int px = blockIdx.x*256 + tid;
    const float* vb = g_v  + (size_t)b*CC*HW + px;
    float*       ob = g_t0 + (size_t)b*CC*HW + px;
#pragma unroll
    for (int h = 0; h < 4; h++) {
        float vr[16];
#pragma unroll
        for (int d = 0; d < 16; d++) vr[d] = vb[(size_t)(h*CH + d)*HW];
#pragma unroll
        for (int c = 0; c < 16; c++) {
            const float4* a4 = reinterpret_cast<const float4*>(sa + h*256 + c*16);
            float s = 0.f;
#pragma unroll
            for (int d4 = 0; d4 < 4; d4++) {
                float4 a = a4[d4];
                s += a.x*vr[d4*4+0] + a.y*vr[d4*4+1] + a.z*vr[d4*4+2] + a.w*vr[d4*4+3];
            }
            ob[(size_t)(h*CH + c)*HW] = s;
        }
    }
}

// ---------------- 3x3 conv via tf32 mma, occupancy-tuned --------------------
// Block 512 = 16 warps (wm 0..3, wn 0..3). Tile 64 oc x 128 px (32w x 4h).
// 8-ic chunks: smem = in[8][232] + w[9][8][72] = 28.2 KB; acc 16 regs/thread.
#define INS 232
#define WS  72
#define S_IN 0
#define S_W  (8*INS)

__global__ void __launch_bounds__(512, 2) k_conv3t(
        const float* __restrict__ in, const u32* __restrict__ wbuf,
        const float* __restrict__ bias, const float* __restrict__ skip,
        const float* __restrict__ skip2, float* __restrict__ out, int do_relu) {
    __shared__ __align__(16) u32 S[8*INS + 9*8*WS];
    int tid = threadIdx.x, lane = tid & 31, wid = tid >> 5;
    int wm = wid & 3, wn = wid >> 2;
    int t4 = lane & 3, g8 = lane >> 2;
    int b = blockIdx.z, gy0 = blockIdx.y*4, gx0 = blockIdx.x*32;
    const float* inb = in + (size_t)b*CC*HW;

    float acc[4][4];
#pragma unroll
    for (int j = 0; j < 4; j++)
#pragma unroll
        for (int r = 0; r < 4; r++) acc[j][r] = 0.f;

    int pb[4];
#pragma unroll
    for (int j = 0; j < 4; j++) {
        int px = wn*32 + j*8 + g8;
        pb[j] = (px >> 5)*34 + (px & 31);
    }

    for (int icb = 0; icb < 64; icb += 8) {
        // input tile [8 ic][6 y][34 x] tf32
        for (int i = tid; i < 8*204; i += 512) {
            int ic = i / 204, r = i - ic*204;
            int yy = r / 34, xx = r - yy*34;
            int iy = gy0 + yy - 1, ix = gx0 + xx - 1;
            float v = 0.f;
            if (iy >= 0 && iy < HH && ix >= 0 && ix < WW)
                v = inb[(size_t)(icb+ic)*HW + iy*WW + ix];
            S[S_IN + ic*INS + yy*34 + xx] = to_tf32(v);
        }
        // weight slab [9 tap][8 ic][oc pad 72], uint4 coalesced
        for (int i4 = tid; i4 < 9*8*16; i4 += 512) {
            int oc4 = i4 & 15, r = i4 >> 4;
            int ic = r & 7, tap = r >> 3;
            uint4 v = *reinterpret_cast<const uint4*>(
                wbuf + tap*4096 + (icb+ic)*64 + oc4*4);
            *reinterpret_cast<uint4*>(S + S_W + (tap*8+ic)*WS + oc4*4) = v;
        }
        __syncthreads();

#pragma unroll 3
        for (int tap = 0; tap < 9; tap++) {
            int sh = (tap/3)*34 + (tap%3);
            int arow = S_W + (tap*8 + t4)*WS + wm*16 + g8;
            u32 a0 = S[arow],        a1 = S[arow + 8];
            u32 a2 = S[arow + 4*WS], a3 = S[arow + 4*WS + 8];
            int ib = S_IN + t4*INS + sh;
#pragma unroll
            for (int j = 0; j < 4; j++) {
                u32 b0 = S[ib + pb[j]];
                u32 b1 = S[ib + 4*INS + pb[j]];
                mma_tf32(acc[j], a0, a1, a2, a3, b0, b1);
            }
        }
        __syncthreads();
    }

    // epilogue
#pragma unroll
    for (int j = 0; j < 4; j++) {
        int p  = wn*32 + j*8 + 2*t4;
        int py = p >> 5, px = p & 31;
        size_t rowidx = (size_t)b*CC*HW + (size_t)(gy0+py)*WW + gx0 + px;
#pragma unroll
        for (int mh = 0; mh < 2; mh++) {
            int oc = wm*16 + g8 + mh*8;
            size_t idx = rowidx + (size_t)oc*HW;
            float v0 = acc[j][mh*2+0] + __ldg(&bias[oc]);
            float v1 = acc[j][mh*2+1] + __ldg(&bias[oc]);
            if (do_relu) { v0 = fmaxf(v0, 0.f); v1 = fmaxf(v1, 0.f); }
            if (skip)  { v0 += skip[idx];  v1 += skip[idx+1]; }
            if (skip2) { v0 += skip2[idx]; v1 += skip2[idx+1]; }
            *reinterpret_cast<float2*>(&out[idx]) = make_float2(v0, v1);
        }
    }
}

// ---------------- launcher ---------------------------------------------------
extern "C" void kernel_launch(void* const* d_in, const int* in_sizes, int n_in,
                              void* d_out, int out_size) {
    const float* x    = (const float*)d_in[0];
    const float* y    = (const float*)d_in[1];
    const float* qw   = (const float*)d_in[2];
    const float* qb   = (const float*)d_in[3];
    const float* kw   = (const float*)d_in[4];
    const float* kb   = (const float*)d_in[5];
    const float* vw   = (const float*)d_in[6];
    const float* vb   = (const float*)d_in[7];
    const float* r1w1 = (const float*)d_in[8];
    const float* r1b1 = (const float*)d_in[9];
    const float* r1w2 = (const float*)d_in[10];
    const float* r1b2 = (const float*)d_in[11];
    const float* r2w1 = (const float*)d_in[12];
    const float* r2b1 = (const float*)d_in[13];
    const float* r2w2 = (const float*)d_in[14];
    const float* r2b2 = (const float*)d_in[15];
    float* outp = (float*)d_out;

    float *pq, *pk, *pt0; u32* pw;
    cudaGetSymbolAddress((void**)&pq,  g_q);
    cudaGetSymbolAddress((void**)&pk,  g_k);
    cudaGetSymbolAddress((void**)&pt0, g_t0);
    cudaGetSymbolAddress((void**)&pw,  g_wbuf);

    k_wprep <<<64, 256>>>(r1w1, r1w2, r2w1, r2w2, qw, kw, vw);
    k_qkvmma<<<dim3(HW/64, BB, 3), 256>>>(x, y, qb, kb, vb);
    k_gram  <<<dim3(32, 32), 256>>>();
    k_applysm<<<dim3(HW/256, BB), 256>>>();

    dim3 cgrid(WW/32, HH/4, BB);
    k_conv3t<<<cgrid, 512>>>(pt0, pw + 0*36864, r1b1, nullptr, nullptr, pq, 1);
    k_conv3t<<<cgrid, 512>>>(pq,  pw + 1*36864, r1b2, pt0,     nullptr, pk, 0);
    k_conv3t<<<cgrid, 512>>>(pk,  pw + 2*36864, r2b1, nullptr, nullptr, pq, 1);
    k_conv3t<<<cgrid, 512>>>(pq,  pw + 3*36864, r2b2, pk,      y,       outp, 0);
}

// round 12
// speedup vs baseline: 1.4228x; 1.4228x over previous
#include <cuda_runtime.h>
#include <cuda_bf16.h>
#include <math.h>

#define BB 8
#define CC 64
#define HEADS 4
#define CH 16
#define HH 256
#define WW 256
#define HW (HH*WW)
#define EPS 1e-12f

typedef unsigned int u32;

// ---------------- static device scratch ----------------
__device__ float g_q [BB*CC*HW];
__device__ float g_k [BB*CC*HW];
__device__ float g_v [BB*CC*HW];
__device__ float g_t0[BB*CC*HW];
__device__ float g_gram[BB*HEADS*CH*CH];
__device__ float g_qn[BB*CC];
__device__ float g_kn[BB*CC];
__device__ __align__(16) u32 g_wbuf [4*9*64*64];  // conv wts [conv][tap][ic][oc] tf32
__device__ __align__(16) u32 g_wqkv[3*64*64];     // qkv  wts [g][ic][oc] tf32

__device__ __forceinline__ u32 to_tf32(float v) {
    u32 t; asm("cvt.rna.tf32.f32 %0, %1;" : "=r"(t) : "f"(v)); return t;
}
__device__ __forceinline__ void mma_tf32(float* d, u32 a0, u32 a1, u32 a2, u32 a3,
                                         u32 b0, u32 b1) {
    asm volatile(
        "mma.sync.aligned.m16n8k8.row.col.f32.tf32.tf32.f32 "
        "{%0,%1,%2,%3}, {%4,%5,%6,%7}, {%8,%9}, {%0,%1,%2,%3};"
        : "+f"(d[0]), "+f"(d[1]), "+f"(d[2]), "+f"(d[3])
        : "r"(a0), "r"(a1), "r"(a2), "r"(a3), "r"(b0), "r"(b1));
}
__device__ __forceinline__ u32 smaddr(const void* p) {
    return (u32)__cvta_generic_to_shared(p);
}
__device__ __forceinline__ void cpa4(u32 dst, const void* src, bool ok) {
    asm volatile("cp.async.ca.shared.global [%0], [%1], 4, %2;"
                 :: "r"(dst), "l"(src), "r"(ok ? 4 : 0) : "memory");
}
__device__ __forceinline__ void cpa16(u32 dst, const void* src) {
    asm volatile("cp.async.cg.shared.global [%0], [%1], 16;"
                 :: "r"(dst), "l"(src) : "memory");
}
#define CP_COMMIT() asm volatile("cp.async.commit_group;" ::: "memory")
#define CP_WAIT1()  asm volatile("cp.async.wait_group 1;" ::: "memory")
#define CP_WAIT0()  asm volatile("cp.async.wait_group 0;" ::: "memory")

// ---------------- weight prep + zeroing (tiny, runs first) ------------------
__global__ void k_wprep(const float* __restrict__ w0, const float* __restrict__ w1,
                        const float* __restrict__ w2, const float* __restrict__ w3,
                        const float* __restrict__ qw, const float* __restrict__ kw,
                        const float* __restrict__ vw) {
    int gtid = blockIdx.x*256 + threadIdx.x;     // 16384 threads
    const float* ws[4] = {w0, w1, w2, w3};
#pragma unroll
    for (int c = 0; c < 4; c++) {
        const float* wp = ws[c];
        for (int e = gtid; e < 9*64*64; e += 16384) {
            int tap = e >> 12, r = e & 4095;
            int ic = r >> 6, oc = r & 63;
            g_wbuf[c*36864 + tap*4096 + ic*64 + oc] = to_tf32(wp[oc*576 + ic*9 + tap]);
        }
    }
    const float* qs[3] = {qw, kw, vw};
#pragma unroll
    for (int g = 0; g < 3; g++) {
        for (int e = gtid; e < 4096; e += 16384) {
            int ic = e >> 6, oc = e & 63;
            g_wqkv[g*4096 + ic*64 + oc] = to_tf32(qs[g][oc*64 + ic]);
        }
    }
    if (gtid < BB*HEADS*CH*CH) g_gram[gtid] = 0.f;
    if (gtid < BB*CC) { g_qn[gtid] = 0.f; g_kn[gtid] = 0.f; }
}

// ---------------- q,k,v 1x1 convs via tf32 MMA ------------------------------
__global__ void __launch_bounds__(256) k_qkvmma(
        const float* __restrict__ x, const float* __restrict__ y,
        const float* __restrict__ qb, const float* __restrict__ kb,
        const float* __restrict__ vb) {
    __shared__ __align__(16) u32 sIn[16*72];
    __shared__ __align__(16) u32 sW [16*72];
    int tid = threadIdx.x, lane = tid & 31, wid = tid >> 5;
    int wm = wid & 3, wn = wid >> 2;
    int t4 = lane & 3, g8 = lane >> 2;
    int g = blockIdx.z, b = blockIdx.y;
    int px0 = blockIdx.x*64;
    const float* in  = (g == 0 ? x : y) + (size_t)b*CC*HW + px0;
    const u32* wsrc  = g_wqkv + g*4096;
    const float* bia = g == 0 ? qb : (g == 1 ? kb : vb);
    float* outp = (g == 0 ? g_q : (g == 1 ? g_k : g_v)) + (size_t)b*CC*HW + px0;

    float acc[4][4];
#pragma unroll
    for (int j = 0; j < 4; j++)
#pragma unroll
        for (int r = 0; r < 4; r++) acc[j][r] = 0.f;

    for (int icb = 0; icb < 64; icb += 16) {
        for (int i = tid; i < 1024; i += 256) {
            int ic = i >> 6, p = i & 63;
            sIn[ic*72 + p] = to_tf32(in[(size_t)(icb+ic)*HW + p]);
        }
        for (int i = tid; i < 1024; i += 256) {
            int ic = i >> 6, oc = i & 63;
            sW[ic*72 + oc] = wsrc[(icb+ic)*64 + oc];
        }
        __syncthreads();
#pragma unroll
        for (int ks = 0; ks < 2; ks++) {
            int arow = (ks*8 + t4)*72 + wm*16 + g8;
            u32 a0 = sW[arow], a1 = sW[arow+8], a2 = sW[arow+4*72], a3 = sW[arow+4*72+8];
            int ib = (ks*8 + t4)*72;
#pragma unroll
            for (int j = 0; j < 4; j++) {
                int px = wn*32 + j*8 + g8;
                u32 b0 = sIn[ib + px], b1 = sIn[ib + 4*72 + px];
                mma_tf32(acc[j], a0, a1, a2, a3, b0, b1);
            }
        }
        __syncthreads();
    }
#pragma unroll
    for (int j = 0; j < 4; j++) {
        int p = wn*32 + j*8 + 2*t4;
#pragma unroll
        for (int mh = 0; mh < 2; mh++) {
            int oc = wm*16 + g8 + mh*8;
            float bv = __ldg(&bia[oc]);
            *reinterpret_cast<float2*>(&outp[(size_t)oc*HW + p]) =
                make_float2(acc[j][mh*2+0] + bv, acc[j][mh*2+1] + bv);
        }
    }
}

// ---------------- gram + norms ----------------------------------------------
__global__ void k_gram() {
    __shared__ float qs[16*65];
    __shared__ float ks[16*65];
    int tid = threadIdx.x;
    int c = tid & 15, d = tid >> 4;
    int bh = blockIdx.y, b = bh >> 2, h = bh & 3;
    const float* qp = g_q + ((size_t)b*CC + h*CH)*HW;
    const float* kp = g_k + ((size_t)b*CC + h*CH)*HW;
    float acc = 0.f, nacc = 0.f;
    for (int t = 0; t < 32; t++) {
        int n0 = blockIdx.x*2048 + t*64;
        for (int idx = tid; idx < 1024; idx += 256) {
            int r = idx >> 6, j = idx & 63;
            qs[r*65 + j] = qp[(size_t)r*HW + n0 + j];
            ks[r*65 + j] = kp[(size_t)r*HW + n0 + j];
        }
        __syncthreads();
#pragma unroll 8
        for (int j = 0; j < 64; j++) acc += qs[c*65 + j] * ks[d*65 + j];
        if (d == 0) {
#pragma unroll 8
            for (int j = 0; j < 64; j++) { float v = qs[c*65 + j]; nacc += v*v; }
        } else if (d == 1) {
#pragma unroll 8
            for (int j = 0; j < 64; j++) { float v = ks[c*65 + j]; nacc += v*v; }
        }
        __syncthreads();
    }
    atomicAdd(&g_gram[bh*256 + c*16 + d], acc);
    if (d == 0) atomicAdd(&g_qn[b*CC + h*CH + c], nacc);
    if (d == 1) atomicAdd(&g_kn[b*CC + h*CH + c], nacc);
}

// ---------------- apply with per-block softmax recompute --------------------
__global__ void k_applysm() {
    __shared__ __align__(16) float sa[HEADS*CH*CH];
    int tid = threadIdx.x;
    int b = blockIdx.y;
    if (tid < 64) {
        int h = tid >> 4, c = tid & 15;
        float nq = fmaxf(sqrtf(g_qn[b*CC + h*CH + c]), EPS);
        float l[16], m = -1e30f;
#pragma unroll
        for (int d = 0; d < 16; d++) {
            float nk = fmaxf(sqrtf(g_kn[b*CC + h*CH + d]), EPS);
            l[d] = g_gram[(b*4+h)*256 + c*16 + d] / (nq * nk);
            m = fmaxf(m, l[d]);
        }
        float s = 0.f;
#pragma unroll
        for (int d = 0; d < 16; d++) { l[d] = expf(l[d] - m); s += l[d]; }
        float inv = 1.f / s;
#pragma unroll
        for (int d = 0; d < 16; d++) sa[h*256 + c*16 + d] = l[d] * inv;
    }
    __syncthreads();
    int px = blockIdx.x*256 + tid;
    const float* vb = g_v  + (size_t)b*CC*HW + px;
    float*       ob = g_t0 + (size_t)b*CC*HW + px;
#pragma unroll
    for (int h = 0; h < 4; h++) {
        float vr[16];
#pragma unroll
        for (int d = 0; d < 16; d++) vr[d] = vb[(size_t)(h*CH + d)*HW];
#pragma unroll
        for (int c = 0; c < 16; c++) {
            const float4* a4 = reinterpret_cast<const float4*>(sa + h*256 + c*16);
            float s = 0.f;
#pragma unroll
            for (int d4 = 0; d4 < 4; d4++) {
                float4 a = a4[d4];
                s += a.x*vr[d4*4+0] + a.y*vr[d4*4+1] + a.z*vr[d4*4+2] + a.w*vr[d4*4+3];
            }
            ob[(size_t)(h*CH + c)*HW] = s;
        }
    }
}

// ---------------- 3x3 conv: tf32 mma + cp.async double buffering ------------
// Block 256 thr = 8 warps (wm 0..3, wn 0..1). Tile 64 oc x 128 px (32w x 4h).
// 8-ic chunks, 2 smem buffers; prefetch chunk c+1 while computing chunk c.
#define INS 232
#define WS  72
#define INB (8*INS)      /* 1856 u32 per input buffer  */
#define WB  (9*8*WS)     /* 5184 u32 per weight buffer */
#define SM_IN(s) ((s)*INB)
#define SM_W(s)  (2*INB + (s)*WB)
#define SMEM_U32C (2*INB + 2*WB)   /* 14080 u32 = 56320 B */

__global__ void __launch_bounds__(256) k_conv3t(
        const float* __restrict__ in, const u32* __restrict__ wbuf,
        const float* __restrict__ bias, const float* __restrict__ skip,
        const float* __restrict__ skip2, float* __restrict__ out, int do_relu) {
    extern __shared__ __align__(16) u32 S[];
    int tid = threadIdx.x, lane = tid & 31, wid = tid >> 5;
    int wm = wid & 3, wn = wid >> 2;
    int t4 = lane & 3, g8 = lane >> 2;
    int b = blockIdx.z, gy0 = blockIdx.y*4, gx0 = blockIdx.x*32;
    const float* inb = in + (size_t)b*CC*HW;
    u32 sbase = smaddr(S);

    float acc[8][4];
#pragma unroll
    for (int j = 0; j < 8; j++)
#pragma unroll
        for (int r = 0; r < 4; r++) acc[j][r] = 0.f;

    int pb[8];
#pragma unroll
    for (int j = 0; j < 8; j++) {
        int px = wn*64 + j*8 + g8;
        pb[j] = (px >> 5)*34 + (px & 31);
    }

    // ---- prefetch helper (chunk cc into buffer s) ----
    auto prefetch = [&](int cc, int s) {
        int icb = cc*8;
        // input tile [8 ic][6 y][34 x], raw f32 bits (tf32-by-truncation)
#pragma unroll
        for (int it = 0; it < 7; it++) {
            int i = tid + it*256;
            if (i < 8*204) {
                int ic = i / 204, r = i - ic*204;
                int yy = r / 34, xx = r - yy*34;
                int iy = gy0 + yy - 1, ix = gx0 + xx - 1;
                bool ok = (iy >= 0 && iy < HH && ix >= 0 && ix < WW);
                const float* src = ok ? (inb + (size_t)(icb+ic)*HW + iy*WW + ix) : inb;
                cpa4(sbase + (SM_IN(s) + ic*INS + yy*34 + xx)*4, src, ok);
            }
        }
        // weight slab [9 tap][8 ic][oc pad 72], 16B ops
#pragma unroll
        for (int it = 0; it < 5; it++) {
            int i4 = tid + it*256;
            if (i4 < 9*8*16) {
                int oc4 = i4 & 15, r = i4 >> 4;
                int ic = r & 7, tap = r >> 3;
                cpa16(sbase + (SM_W(s) + (tap*8+ic)*WS + oc4*4)*4,
                      wbuf + tap*4096 + (icb+ic)*64 + oc4*4);
            }
        }
        CP_COMMIT();
    };

    prefetch(0, 0);
    for (int c = 0; c < 8; c++) {
        int s = c & 1;
        if (c < 7) prefetch(c+1, s^1);
        if (c < 7) { CP_WAIT1(); } else { CP_WAIT0(); }
        __syncthreads();

        const u32* In = S + SM_IN(s);
        const u32* W  = S + SM_W(s);
#pragma unroll 3
        for (int tap = 0; tap < 9; tap++) {
            int sh = (tap/3)*34 + (tap%3);
            int arow = (tap*8 + t4)*WS + wm*16 + g8;
            u32 a0 = W[arow],        a1 = W[arow + 8];
            u32 a2 = W[arow + 4*WS], a3 = W[arow + 4*WS + 8];
            int ib = t4*INS + sh;
#pragma unroll
            for (int j = 0; j < 8; j++) {
                u32 b0 = In[ib + pb[j]];
                u32 b1 = In[ib + 4*INS + pb[j]];
                mma_tf32(acc[j], a0, a1, a2, a3, b0, b1);
            }
        }
        __syncthreads();
    }

    // ---- epilogue ----
#pragma unroll
    for (int j = 0; j < 8; j++) {
        int p  = wn*64 + j*8 + 2*t4;
        int py = p >> 5, px = p & 31;
        size_t rowidx = (size_t)b*CC*HW + (size_t)(gy0+py)*WW + gx0 + px;
#pragma unroll
        for (int mh = 0; mh < 2; mh++) {
            int oc = wm*16 + g8 + mh*8;
            size_t idx = rowidx + (size_t)oc*HW;
            float v0 = acc[j][mh*2+0] + __ldg(&bias[oc]);
            float v1 = acc[j][mh*2+1] + __ldg(&bias[oc]);
            if (do_relu) { v0 = fmaxf(v0, 0.f); v1 = fmaxf(v1, 0.f); }
            if (skip)  { v0 += skip[idx];  v1 += skip[idx+1]; }
            if (skip2) { v0 += skip2[idx]; v1 += skip2[idx+1]; }
            *reinterpret_cast<float2*>(&out[idx]) = make_float2(v0, v1);
        }
    }
}

// ---------------- launcher ---------------------------------------------------
extern "C" void kernel_launch(void* const* d_in, const int* in_sizes, int n_in,
                              void* d_out, int out_size) {
    const float* x    = (const float*)d_in[0];
    const float* y    = (const float*)d_in[1];
    const float* qw   = (const float*)d_in[2];
    const float* qb   = (const float*)d_in[3];
    const float* kw   = (const float*)d_in[4];
    const float* kb   = (const float*)d_in[5];
    const float* vw   = (const float*)d_in[6];
    const float* vb   = (const float*)d_in[7];
    const float* r1w1 = (const float*)d_in[8];
    const float* r1b1 = (const float*)d_in[9];
    const float* r1w2 = (const float*)d_in[10];
    const float* r1b2 = (const float*)d_in[11];
    const float* r2w1 = (const float*)d_in[12];
    const float* r2b1 = (const float*)d_in[13];
    const float* r2w2 = (const float*)d_in[14];
    const float* r2b2 = (const float*)d_in[15];
    float* outp = (float*)d_out;

    float *pq, *pk, *pt0; u32* pw;
    cudaGetSymbolAddress((void**)&pq,  g_q);
    cudaGetSymbolAddress((void**)&pk,  g_k);
    cudaGetSymbolAddress((void**)&pt0, g_t0);
    cudaGetSymbolAddress((void**)&pw,  g_wbuf);

    static int smem_set = 0;
    int smem_bytes = SMEM_U32C * 4;
    if (!smem_set) {
        cudaFuncSetAttribute(k_conv3t, cudaFuncAttributeMaxDynamicSharedMemorySize, smem_bytes);
        smem_set = 1;
    }

    k_wprep <<<64, 256>>>(r1w1, r1w2, r2w1, r2w2, qw, kw, vw);
    k_qkvmma<<<dim3(HW/64, BB, 3), 256>>>(x, y, qb, kb, vb);
    k_gram  <<<dim3(32, 32), 256>>>();
    k_applysm<<<dim3(HW/256, BB), 256>>>();

    dim3 cgrid(WW/32, HH/4, BB);
    k_conv3t<<<cgrid, 256, smem_bytes>>>(pt0, pw + 0*36864, r1b1, nullptr, nullptr, pq, 1);
    k_conv3t<<<cgrid, 256, smem_bytes>>>(pq,  pw + 1*36864, r1b2, pt0,     nullptr, pk, 0);
    k_conv3t<<<cgrid, 256, smem_bytes>>>(pk,  pw + 2*36864, r2b1, nullptr, nullptr, pq, 1);
    k_conv3t<<<cgrid, 256, smem_bytes>>>(pq,  pw + 3*36864, r2b2, pk,      y,       outp, 0);
}

// round 13
// speedup vs baseline: 1.7266x; 1.2135x over previous
#include <cuda_runtime.h>
#include <cuda_bf16.h>
#include <math.h>

#define BB 8
#define CC 64
#define HEADS 4
#define CH 16
#define HH 256
#define WW 256
#define HW (HH*WW)
#define EPS 1e-12f

typedef unsigned int u32;

// ---------------- static device scratch ----------------
__device__ float g_q [BB*CC*HW];   // conv scratch
__device__ float g_k [BB*CC*HW];   // conv scratch
__device__ float g_v [BB*CC*HW];
__device__ float g_t0[BB*CC*HW];
__device__ float g_gram[BB*HEADS*CH*CH];
__device__ float g_qn[BB*CC];
__device__ float g_kn[BB*CC];
__device__ __align__(16) u32 g_wbuf [4*9*64*64];  // conv wts [conv][tap][ic][oc] tf32
__device__ __align__(16) u32 g_wqkv[3*64*64];     // qkv  wts [g][ic][oc] tf32

__device__ __forceinline__ u32 to_tf32(float v) {
    u32 t; asm("cvt.rna.tf32.f32 %0, %1;" : "=r"(t) : "f"(v)); return t;
}
__device__ __forceinline__ void mma_tf32(float* d, u32 a0, u32 a1, u32 a2, u32 a3,
                                         u32 b0, u32 b1) {
    asm volatile(
        "mma.sync.aligned.m16n8k8.row.col.f32.tf32.tf32.f32 "
        "{%0,%1,%2,%3}, {%4,%5,%6,%7}, {%8,%9}, {%0,%1,%2,%3};"
        : "+f"(d[0]), "+f"(d[1]), "+f"(d[2]), "+f"(d[3])
        : "r"(a0), "r"(a1), "r"(a2), "r"(a3), "r"(b0), "r"(b1));
}
__device__ __forceinline__ u32 smaddr(const void* p) {
    return (u32)__cvta_generic_to_shared(p);
}
__device__ __forceinline__ void cpa4(u32 dst, const void* src, bool ok) {
    asm volatile("cp.async.ca.shared.global [%0], [%1], 4, %2;"
                 :: "r"(dst), "l"(src), "r"(ok ? 4 : 0) : "memory");
}
__device__ __forceinline__ void cpa16(u32 dst, const void* src) {
    asm volatile("cp.async.cg.shared.global [%0], [%1], 16;"
                 :: "r"(dst), "l"(src) : "memory");
}
#define CP_COMMIT() asm volatile("cp.async.commit_group;" ::: "memory")
#define CP_WAIT1()  asm volatile("cp.async.wait_group 1;" ::: "memory")
#define CP_WAIT0()  asm volatile("cp.async.wait_group 0;" ::: "memory")

// ---------------- weight prep + zeroing (tiny, runs first) ------------------
__global__ void k_wprep(const float* __restrict__ w0, const float* __restrict__ w1,
                        const float* __restrict__ w2, const float* __restrict__ w3,
                        const float* __restrict__ qw, const float* __restrict__ kw,
                        const float* __restrict__ vw) {
    int gtid = blockIdx.x*256 + threadIdx.x;     // 16384 threads
    const float* ws[4] = {w0, w1, w2, w3};
#pragma unroll
    for (int c = 0; c < 4; c++) {
        const float* wp = ws[c];
        for (int e = gtid; e < 9*64*64; e += 16384) {
            int tap = e >> 12, r = e & 4095;
            int ic = r >> 6, oc = r & 63;
            g_wbuf[c*36864 + tap*4096 + ic*64 + oc] = to_tf32(wp[oc*576 + ic*9 + tap]);
        }
    }
    const float* qs[3] = {qw, kw, vw};
#pragma unroll
    for (int g = 0; g < 3; g++) {
        for (int e = gtid; e < 4096; e += 16384) {
            int ic = e >> 6, oc = e & 63;
            g_wqkv[g*4096 + ic*64 + oc] = to_tf32(qs[g][oc*64 + ic]);
        }
    }
    if (gtid < BB*HEADS*CH*CH) g_gram[gtid] = 0.f;
    if (gtid < BB*CC) { g_qn[gtid] = 0.f; g_kn[gtid] = 0.f; }
}

// ---------------- fused qkv + gram + norms ----------------------------------
// Block 256 = 8 warps (wm 0..3, wn 0..1). 64-px slab. q,k stay in smem;
// only v goes to DRAM. Gram partial via tf32 MMA, merged by atomics.
#define SP 68
#define FX(s) ((s)*5632)
#define FY(s) (FX(s)+1088)
#define FW(s) (FX(s)+2176)
#define FQ    11264
#define FKT   15616
#define F_TOT 19968            /* u32 -> 79872 B dynamic smem */

__global__ void __launch_bounds__(256) k_front(
        const float* __restrict__ x, const float* __restrict__ y,
        const float* __restrict__ qb, const float* __restrict__ kb,
        const float* __restrict__ vb) {
    extern __shared__ __align__(16) u32 S[];
    int tid = threadIdx.x, lane = tid & 31, wid = tid >> 5;
    int wm = wid & 3, wn = wid >> 2;
    int t4 = lane & 3, g8 = lane >> 2;
    int b = blockIdx.y;
    int px0 = blockIdx.x*64;
    const float* xb = x + (size_t)b*CC*HW + px0;
    const float* yb = y + (size_t)b*CC*HW + px0;
    u32 sbase = smaddr(S);

    float aQ[4][4], aK[4][4], aV[4][4];
#pragma unroll
    for (int j = 0; j < 4; j++)
#pragma unroll
        for (int r = 0; r < 4; r++) { aQ[j][r] = 0.f; aK[j][r] = 0.f; aV[j][r] = 0.f; }

    auto prefetch = [&](int cc, int s) {
        int icb = cc*16;
        // x,y tiles: raw f32 bits, 16B ops (2 per thread)
#pragma unroll
        for (int it = 0; it < 2; it++) {
            int i = tid + it*256;                // 0..511
            int mat = i >> 8, r = i & 255;
            int ic = r >> 4, seg = r & 15;
            const float* src = (mat ? yb : xb) + (size_t)(icb+ic)*HW + seg*4;
            cpa16(sbase + ((mat ? FY(s) : FX(s)) + ic*SP + seg*4)*4, src);
        }
        // weights: 3 mats x 16 ic x 16 segs (3 per thread)
#pragma unroll
        for (int it = 0; it < 3; it++) {
            int i = tid + it*256;                // 0..767
            int g = i >> 8, r = i & 255;
            int ic = r >> 4, seg = r & 15;
            cpa16(sbase + (FW(s) + g*1152 + ic*72 + seg*4)*4,
                  g_wqkv + g*4096 + (icb+ic)*64 + seg*4);
        }
        CP_COMMIT();
    };

    prefetch(0, 0);
    for (int c = 0; c < 4; c++) {
        int s = c & 1;
        if (c < 3) prefetch(c+1, s^1);
        if (c < 3) { CP_WAIT1(); } else { CP_WAIT0(); }
        __syncthreads();
        const u32* X = S + FX(s);
        const u32* Y = S + FY(s);
        const u32* W = S + FW(s);
#pragma unroll
        for (int ks = 0; ks < 2; ks++) {
            int ar = (ks*8 + t4)*72 + wm*16 + g8;
            u32 qa0 = W[ar],        qa1 = W[ar+8];
            u32 qa2 = W[ar+4*72],   qa3 = W[ar+4*72+8];
            u32 ka0 = W[1152+ar],      ka1 = W[1152+ar+8];
            u32 ka2 = W[1152+ar+4*72], ka3 = W[1152+ar+4*72+8];
            u32 va0 = W[2304+ar],      va1 = W[2304+ar+8];
            u32 va2 = W[2304+ar+4*72], va3 = W[2304+ar+4*72+8];
            int ib = (ks*8 + t4)*SP;
#pragma unroll
            for (int j = 0; j < 4; j++) {
                int px = wn*32 + j*8 + g8;
                u32 bx0 = X[ib + px], bx1 = X[ib + 4*SP + px];
                u32 by0 = Y[ib + px], by1 = Y[ib + 4*SP + px];
                mma_tf32(aQ[j], qa0, qa1, qa2, qa3, bx0, bx1);
                mma_tf32(aK[j], ka0, ka1, ka2, ka3, by0, by1);
                mma_tf32(aV[j], va0, va1, va2, va3, by0, by1);
            }
        }
        __syncthreads();
    }

    // epilogue: q -> sQ[ch][px], k -> sKT[px][ch], v -> gmem
    float* vout = g_v + (size_t)b*CC*HW + px0;
#pragma unroll
    for (int j = 0; j < 4; j++) {
        int p = wn*32 + j*8 + 2*t4;
#pragma unroll
        for (int mh = 0; mh < 2; mh++) {
            int oc = wm*16 + g8 + mh*8;
            float qv = __ldg(&qb[oc]), kv = __ldg(&kb[oc]), vv = __ldg(&vb[oc]);
            float q0 = aQ[j][mh*2+0] + qv, q1 = aQ[j][mh*2+1] + qv;
            float k0 = aK[j][mh*2+0] + kv, k1 = aK[j][mh*2+1] + kv;
            S[FQ  + oc*SP + p]     = __float_as_uint(q0);
            S[FQ  + oc*SP + p + 1] = __float_as_uint(q1);
            S[FKT + p*SP + oc]     = __float_as_uint(k0);
            S[FKT + (p+1)*SP + oc] = __float_as_uint(k1);
            *reinterpret_cast<float2*>(&vout[(size_t)oc*HW + p]) =
                make_float2(aV[j][mh*2+0] + vv, aV[j][mh*2+1] + vv);
        }
    }
    __syncthreads();

    // gram partial: warp -> (head, n-half); 8 tf32 MMAs contract over 64 px
    {
        int h = wid >> 1, nb = (wid & 1)*8;
        float G[4] = {0.f, 0.f, 0.f, 0.f};
        const u32* Q  = S + FQ;
        const u32* KT = S + FKT;
#pragma unroll
        for (int k0 = 0; k0 < 8; k0++) {
            int ar = (h*16 + g8)*SP + k0*8 + t4;
            u32 a0 = Q[ar],        a1 = Q[ar + 8*SP];
            u32 a2 = Q[ar + 4],    a3 = Q[ar + 8*SP + 4];
            int br = (k0*8 + t4)*SP + h*16 + nb + g8;
            u32 b0 = KT[br], b1 = KT[br + 4*SP];
            mma_tf32(G, a0, a1, a2, a3, b0, b1);
        }
        float* gg = &g_gram[((size_t)b*4 + h)*256];
        atomicAdd(&gg[(g8)*16   + nb + 2*t4],     G[0]);
        atomicAdd(&gg[(g8)*16   + nb + 2*t4 + 1], G[1]);
        atomicAdd(&gg[(g8+8)*16 + nb + 2*t4],     G[2]);
        atomicAdd(&gg[(g8+8)*16 + nb + 2*t4 + 1], G[3]);
    }
    // norm partials
    if (tid < 64) {
        float s = 0.f;
#pragma unroll 8
        for (int px = 0; px < 64; px++) {
            float v = __uint_as_float(S[FQ + tid*SP + px]); s += v*v;
        }
        atomicAdd(&g_qn[b*64 + tid], s);
    } else if (tid < 128) {
        int ch = tid - 64;
        float s = 0.f;
#pragma unroll 8
        for (int px = 0; px < 64; px++) {
            float v = __uint_as_float(S[FKT + px*SP + ch]); s += v*v;
        }
        atomicAdd(&g_kn[b*64 + ch], s);
    }
}

// ---------------- apply with per-block softmax recompute --------------------
__global__ void k_applysm() {
    __shared__ __align__(16) float sa[HEADS*CH*CH];
    int tid = threadIdx.x;
    int b = blockIdx.y;
    if (tid < 64) {
        int h = tid >> 4, c = tid & 15;
        float nq = fmaxf(sqrtf(g_qn[b*CC + h*CH + c]), EPS);
        float l[16], m = -1e30f;
#pragma unroll
        for (int d = 0; d < 16; d++) {
            float nk = fmaxf(sqrtf(g_kn[b*CC + h*CH + d]), EPS);
            l[d] = g_gram[(b*4+h)*256 + c*16 + d] / (nq * nk);
            m = fmaxf(m, l[d]);
        }
        float s = 0.f;
#pragma unroll
        for (int d = 0; d < 16; d++) { l[d] = expf(l[d] - m); s += l[d]; }
        float inv = 1.f / s;
#pragma unroll
        for (int d = 0; d < 16; d++) sa[h*256 + c*16 + d] = l[d] * inv;
    }
    __syncthreads();
    int px = blockIdx.x*256 + tid;
    const float* vb = g_v  + (size_t)b*CC*HW + px;
    float*       ob = g_t0 + (size_t)b*CC*HW + px;
#pragma unroll
    for (int h = 0; h < 4; h++) {
        float vr[16];
#pragma unroll
        for (int d = 0; d < 16; d++) vr[d] = vb[(size_t)(h*CH + d)*HW];
#pragma unroll
        for (int c = 0; c < 16; c++) {
            const float4* a4 = reinterpret_cast<const float4*>(sa + h*256 + c*16);
            float s = 0.f;
#pragma unroll
            for (int d4 = 0; d4 < 4; d4++) {
                float4 a = a4[d4];
                s += a.x*vr[d4*4+0] + a.y*vr[d4*4+1] + a.z*vr[d4*4+2] + a.w*vr[d4*4+3];
            }
            ob[(size_t)(h*CH + c)*HW] = s;
        }
    }
}

// ---------------- 3x3 conv: tf32 mma + cp.async double buffering ------------
#define INS 232
#define WS  72
#define INB (8*INS)
#define WB  (9*8*WS)
#define SM_IN(s) ((s)*INB)
#define SM_W(s)  (2*INB + (s)*WB)
#define SMEM_U32C (2*INB + 2*WB)

__global__ void __launch_bounds__(256) k_conv3t(
        const float* __restrict__ in, const u32* __restrict__ wbuf,
        const float* __restrict__ bias, const float* __restrict__ skip,
        const float* __restrict__ skip2, float* __restrict__ out, int do_relu) {
    extern __shared__ __align__(16) u32 S[];
    int tid = threadIdx.x, lane = tid & 31, wid = tid >> 5;
    int wm = wid & 3, wn = wid >> 2;
    int t4 = lane & 3, g8 = lane >> 2;
    int b = blockIdx.z, gy0 = blockIdx.y*4, gx0 = blockIdx.x*32;
    const float* inb = in + (size_t)b*CC*HW;
    u32 sbase = smaddr(S);

    float acc[8][4];
#pragma unroll
    for (int j = 0; j < 8; j++)
#pragma unroll
        for (int r = 0; r < 4; r++) acc[j][r] = 0.f;

    int pb[8];
#pragma unroll
    for (int j = 0; j < 8; j++) {
        int px = wn*64 + j*8 + g8;
        pb[j] = (px >> 5)*34 + (px & 31);
    }

    auto prefetch = [&](int cc, int s) {
        int icb = cc*8;
#pragma unroll
        for (int it = 0; it < 7; it++) {
            int i = tid + it*256;
            if (i < 8*204) {
                int ic = i / 204, r = i - ic*204;
                int yy = r / 34, xx = r - yy*34;
                int iy = gy0 + yy - 1, ix = gx0 + xx - 1;
                bool ok = (iy >= 0 && iy < HH && ix >= 0 && ix < WW);
                const float* src = ok ? (inb + (size_t)(icb+ic)*HW + iy*WW + ix) : inb;
                cpa4(sbase + (SM_IN(s) + ic*INS + yy*34 + xx)*4, src, ok);
            }
        }
#pragma unroll
        for (int it = 0; it < 5; it++) {
            int i4 = tid + it*256;
            if (i4 < 9*8*16) {
                int oc4 = i4 & 15, r = i4 >> 4;
                int ic = r & 7, tap = r >> 3;
                cpa16(sbase + (SM_W(s) + (tap*8+ic)*WS + oc4*4)*4,
                      wbuf + tap*4096 + (icb+ic)*64 + oc4*4);
            }
        }
        CP_COMMIT();
    };

    prefetch(0, 0);
    for (int c = 0; c < 8; c++) {
        int s = c & 1;
        if (c < 7) prefetch(c+1, s^1);
        if (c < 7) { CP_WAIT1(); } else { CP_WAIT0(); }
        __syncthreads();

        const u32* In = S + SM_IN(s);
        const u32* W  = S + SM_W(s);
#pragma unroll 3
        for (int tap = 0; tap < 9; tap++) {
            int sh = (tap/3)*34 + (tap%3);
            int arow = (tap*8 + t4)*WS + wm*16 + g8;
            u32 a0 = W[arow],        a1 = W[arow + 8];
            u32 a2 = W[arow + 4*WS], a3 = W[arow + 4*WS + 8];
            int ib = t4*INS + sh;
#pragma unroll
            for (int j = 0; j < 8; j++) {
                u32 b0 = In[ib + pb[j]];
                u32 b1 = In[ib + 4*INS + pb[j]];
                mma_tf32(acc[j], a0, a1, a2, a3, b0, b1);
            }
        }
        __syncthreads();
    }

#pragma unroll
    for (int j = 0; j < 8; j++) {
        int p  = wn*64 + j*8 + 2*t4;
        int py = p >> 5, px = p & 31;
        size_t rowidx = (size_t)b*CC*HW + (size_t)(gy0+py)*WW + gx0 + px;
#pragma unroll
        for (int mh = 0; mh < 2; mh++) {
            int oc = wm*16 + g8 + mh*8;
            size_t idx = rowidx + (size_t)oc*HW;
            float v0 = acc[j][mh*2+0] + __ldg(&bias[oc]);
            float v1 = acc[j][mh*2+1] + __ldg(&bias[oc]);
            if (do_relu) { v0 = fmaxf(v0, 0.f); v1 = fmaxf(v1, 0.f); }
            if (skip)  { v0 += skip[idx];  v1 += skip[idx+1]; }
            if (skip2) { v0 += skip2[idx]; v1 += skip2[idx+1]; }
            *reinterpret_cast<float2*>(&out[idx]) = make_float2(v0, v1);
        }
    }
}

// ---------------- launcher ---------------------------------------------------
extern "C" void kernel_launch(void* const* d_in, const int* in_sizes, int n_in,
                              void* d_out, int out_size) {
    const float* x    = (const float*)d_in[0];
    const float* y    = (const float*)d_in[1];
    const float* qw   = (const float*)d_in[2];
    const float* qb   = (const float*)d_in[3];
    const float* kw   = (const float*)d_in[4];
    const float* kb   = (const float*)d_in[5];
    const float* vw   = (const float*)d_in[6];
    const float* vb   = (const float*)d_in[7];
    const float* r1w1 = (const float*)d_in[8];
    const float* r1b1 = (const float*)d_in[9];
    const float* r1w2 = (const float*)d_in[10];
    const float* r1b2 = (const float*)d_in[11];
    const float* r2w1 = (const float*)d_in[12];
    const float* r2b1 = (const float*)d_in[13];
    const float* r2w2 = (const float*)d_in[14];
    const float* r2b2 = (const float*)d_in[15];
    float* outp = (float*)d_out;

    float *pq, *pk, *pt0; u32* pw;
    cudaGetSymbolAddress((void**)&pq,  g_q);
    cudaGetSymbolAddress((void**)&pk,  g_k);
    cudaGetSymbolAddress((void**)&pt0, g_t0);
    cudaGetSymbolAddress((void**)&pw,  g_wbuf);

    static int smem_set = 0;
    int conv_smem  = SMEM_U32C * 4;
    int front_smem = F_TOT * 4;
    if (!smem_set) {
        cudaFuncSetAttribute(k_conv3t, cudaFuncAttributeMaxDynamicSharedMemorySize, conv_smem);
        cudaFuncSetAttribute(k_front,  cudaFuncAttributeMaxDynamicSharedMemorySize, front_smem);
        smem_set = 1;
    }

    k_wprep <<<64, 256>>>(r1w1, r1w2, r2w1, r2w2, qw, kw, vw);
    k_front <<<dim3(HW/64, BB), 256, front_smem>>>(x, y, qb, kb, vb);
    k_applysm<<<dim3(HW/256, BB), 256>>>();

    dim3 cgrid(WW/32, HH/4, BB);
    k_conv3t<<<cgrid, 256, conv_smem>>>(pt0, pw + 0*36864, r1b1, nullptr, nullptr, pq, 1);
    k_conv3t<<<cgrid, 256, conv_smem>>>(pq,  pw + 1*36864, r1b2, pt0,     nullptr, pk, 0);
    k_conv3t<<<cgrid, 256, conv_smem>>>(pk,  pw + 2*36864, r2b1, nullptr, nullptr, pq, 1);
    k_conv3t<<<cgrid, 256, conv_smem>>>(pq,  pw + 3*36864, r2b2, pk,      y,       outp, 0);
}

// round 14
// speedup vs baseline: 2.1064x; 1.2199x over previous
#include <cuda_runtime.h>
#include <cuda_bf16.h>
#include <math.h>

#define BB 8
#define CC 64
#define HEADS 4
#define CH 16
#define HH 256
#define WW 256
#define HW (HH*WW)
#define EPS 1e-12f

typedef unsigned int u32;

// ---------------- static device scratch ----------------
__device__ float g_q [BB*CC*HW];   // conv scratch
__device__ float g_k [BB*CC*HW];   // conv scratch
__device__ float g_v [BB*CC*HW];
__device__ float g_t0[BB*CC*HW];
__device__ float g_gram[BB*HEADS*CH*CH];
__device__ float g_qn[BB*CC];
__device__ float g_kn[BB*CC];
__device__ __align__(16) u32 g_wbuf [4*9*64*64];  // conv wts [conv][tap][ic][oc] tf32
__device__ __align__(16) u32 g_wqkv[3*64*64];     // qkv  wts [g][ic][oc] tf32

__device__ __forceinline__ u32 to_tf32(float v) {
    u32 t; asm("cvt.rna.tf32.f32 %0, %1;" : "=r"(t) : "f"(v)); return t;
}
__device__ __forceinline__ void mma_tf32(float* d, u32 a0, u32 a1, u32 a2, u32 a3,
                                         u32 b0, u32 b1) {
    asm volatile(
        "mma.sync.aligned.m16n8k8.row.col.f32.tf32.tf32.f32 "
        "{%0,%1,%2,%3}, {%4,%5,%6,%7}, {%8,%9}, {%0,%1,%2,%3};"
        : "+f"(d[0]), "+f"(d[1]), "+f"(d[2]), "+f"(d[3])
        : "r"(a0), "r"(a1), "r"(a2), "r"(a3), "r"(b0), "r"(b1));
}
__device__ __forceinline__ u32 smaddr(const void* p) {
    return (u32)__cvta_generic_to_shared(p);
}
__device__ __forceinline__ void cpa16(u32 dst, const void* src) {
    asm volatile("cp.async.cg.shared.global [%0], [%1], 16;"
                 :: "r"(dst), "l"(src) : "memory");
}
__device__ __forceinline__ void cpa16z(u32 dst, const void* src, bool ok) {
    asm volatile("cp.async.cg.shared.global [%0], [%1], 16, %2;"
                 :: "r"(dst), "l"(src), "r"(ok ? 16 : 0) : "memory");
}
#define CP_COMMIT() asm volatile("cp.async.commit_group;" ::: "memory")
#define CP_WAIT1()  asm volatile("cp.async.wait_group 1;" ::: "memory")
#define CP_WAIT0()  asm volatile("cp.async.wait_group 0;" ::: "memory")

// ---------------- weight prep + zeroing (tiny, runs first) ------------------
__global__ void k_wprep(const float* __restrict__ w0, const float* __restrict__ w1,
                        const float* __restrict__ w2, const float* __restrict__ w3,
                        const float* __restrict__ qw, const float* __restrict__ kw,
                        const float* __restrict__ vw) {
    int gtid = blockIdx.x*256 + threadIdx.x;     // 16384 threads
    const float* ws[4] = {w0, w1, w2, w3};
#pragma unroll
    for (int c = 0; c < 4; c++) {
        const float* wp = ws[c];
        for (int e = gtid; e < 9*64*64; e += 16384) {
            int tap = e >> 12, r = e & 4095;
            int ic = r >> 6, oc = r & 63;
            g_wbuf[c*36864 + tap*4096 + ic*64 + oc] = to_tf32(wp[oc*576 + ic*9 + tap]);
        }
    }
    const float* qs[3] = {qw, kw, vw};
#pragma unroll
    for (int g = 0; g < 3; g++) {
        for (int e = gtid; e < 4096; e += 16384) {
            int ic = e >> 6, oc = e & 63;
            g_wqkv[g*4096 + ic*64 + oc] = to_tf32(qs[g][oc*64 + ic]);
        }
    }
    if (gtid < BB*HEADS*CH*CH) g_gram[gtid] = 0.f;
    if (gtid < BB*CC) { g_qn[gtid] = 0.f; g_kn[gtid] = 0.f; }
}

// ---------------- fused qkv + gram + norms ----------------------------------
#define SP 68
#define FX(s) ((s)*5632)
#define FY(s) (FX(s)+1088)
#define FW(s) (FX(s)+2176)
#define FQ    11264
#define FKT   15616
#define F_TOT 19968            /* u32 -> 79872 B dynamic smem */

__global__ void __launch_bounds__(256) k_front(
        const float* __restrict__ x, const float* __restrict__ y,
        const float* __restrict__ qb, const float* __restrict__ kb,
        const float* __restrict__ vb) {
    extern __shared__ __align__(16) u32 S[];
    int tid = threadIdx.x, lane = tid & 31, wid = tid >> 5;
    int wm = wid & 3, wn = wid >> 2;
    int t4 = lane & 3, g8 = lane >> 2;
    int b = blockIdx.y;
    int px0 = blockIdx.x*64;
    const float* xb = x + (size_t)b*CC*HW + px0;
    const float* yb = y + (size_t)b*CC*HW + px0;
    u32 sbase = smaddr(S);

    float aQ[4][4], aK[4][4], aV[4][4];
#pragma unroll
    for (int j = 0; j < 4; j++)
#pragma unroll
        for (int r = 0; r < 4; r++) { aQ[j][r] = 0.f; aK[j][r] = 0.f; aV[j][r] = 0.f; }

    auto prefetch = [&](int cc, int s) {
        int icb = cc*16;
#pragma unroll
        for (int it = 0; it < 2; it++) {
            int i = tid + it*256;
            int mat = i >> 8, r = i & 255;
            int ic = r >> 4, seg = r & 15;
            const float* src = (mat ? yb : xb) + (size_t)(icb+ic)*HW + seg*4;
            cpa16(sbase + ((mat ? FY(s) : FX(s)) + ic*SP + seg*4)*4, src);
        }
#pragma unroll
        for (int it = 0; it < 3; it++) {
            int i = tid + it*256;
            int g = i >> 8, r = i & 255;
            int ic = r >> 4, seg = r & 15;
            cpa16(sbase + (FW(s) + g*1152 + ic*72 + seg*4)*4,
                  g_wqkv + g*4096 + (icb+ic)*64 + seg*4);
        }
        CP_COMMIT();
    };

    prefetch(0, 0);
    for (int c = 0; c < 4; c++) {
        int s = c & 1;
        if (c < 3) prefetch(c+1, s^1);
        if (c < 3) { CP_WAIT1(); } else { CP_WAIT0(); }
        __syncthreads();
        const u32* X = S + FX(s);
        const u32* Y = S + FY(s);
        const u32* W = S + FW(s);
#pragma unroll
        for (int ks = 0; ks < 2; ks++) {
            int ar = (ks*8 + t4)*72 + wm*16 + g8;
            u32 qa0 = W[ar],        qa1 = W[ar+8];
            u32 qa2 = W[ar+4*72],   qa3 = W[ar+4*72+8];
            u32 ka0 = W[1152+ar],      ka1 = W[1152+ar+8];
            u32 ka2 = W[1152+ar+4*72], ka3 = W[1152+ar+4*72+8];
            u32 va0 = W[2304+ar],      va1 = W[2304+ar+8];
            u32 va2 = W[2304+ar+4*72], va3 = W[2304+ar+4*72+8];
            int ib = (ks*8 + t4)*SP;
#pragma unroll
            for (int j = 0; j < 4; j++) {
                int px = wn*32 + j*8 + g8;
                u32 bx0 = X[ib + px], bx1 = X[ib + 4*SP + px];
                u32 by0 = Y[ib + px], by1 = Y[ib + 4*SP + px];
                mma_tf32(aQ[j], qa0, qa1, qa2, qa3, bx0, bx1);
                mma_tf32(aK[j], ka0, ka1, ka2, ka3, by0, by1);
                mma_tf32(aV[j], va0, va1, va2, va3, by0, by1);
            }
        }
        __syncthreads();
    }

    float* vout = g_v + (size_t)b*CC*HW + px0;
#pragma unroll
    for (int j = 0; j < 4; j++) {
        int p = wn*32 + j*8 + 2*t4;
#pragma unroll
        for (int mh = 0; mh < 2; mh++) {
            int oc = wm*16 + g8 + mh*8;
            float qv = __ldg(&qb[oc]), kv = __ldg(&kb[oc]), vv = __ldg(&vb[oc]);
            float q0 = aQ[j][mh*2+0] + qv, q1 = aQ[j][mh*2+1] + qv;
            float k0 = aK[j][mh*2+0] + kv, k1 = aK[j][mh*2+1] + kv;
            S[FQ  + oc*SP + p]     = __float_as_uint(q0);
            S[FQ  + oc*SP + p + 1] = __float_as_uint(q1);
            S[FKT + p*SP + oc]     = __float_as_uint(k0);
            S[FKT + (p+1)*SP + oc] = __float_as_uint(k1);
            *reinterpret_cast<float2*>(&vout[(size_t)oc*HW + p]) =
                make_float2(aV[j][mh*2+0] + vv, aV[j][mh*2+1] + vv);
        }
    }
    __syncthreads();

    {
        int h = wid >> 1, nb = (wid & 1)*8;
        float G[4] = {0.f, 0.f, 0.f, 0.f};
        const u32* Q  = S + FQ;
        const u32* KT = S + FKT;
#pragma unroll
        for (int k0 = 0; k0 < 8; k0++) {
            int ar = (h*16 + g8)*SP + k0*8 + t4;
            u32 a0 = Q[ar],        a1 = Q[ar + 8*SP];
            u32 a2 = Q[ar + 4],    a3 = Q[ar + 8*SP + 4];
            int br = (k0*8 + t4)*SP + h*16 + nb + g8;
            u32 b0 = KT[br], b1 = KT[br + 4*SP];
            mma_tf32(G, a0, a1, a2, a3, b0, b1);
        }
        float* gg = &g_gram[((size_t)b*4 + h)*256];
        atomicAdd(&gg[(g8)*16   + nb + 2*t4],     G[0]);
        atomicAdd(&gg[(g8)*16   + nb + 2*t4 + 1], G[1]);
        atomicAdd(&gg[(g8+8)*16 + nb + 2*t4],     G[2]);
        atomicAdd(&gg[(g8+8)*16 + nb + 2*t4 + 1], G[3]);
    }
    if (tid < 64) {
        float s = 0.f;
#pragma unroll 8
        for (int px = 0; px < 64; px++) {
            float v = __uint_as_float(S[FQ + tid*SP + px]); s += v*v;
        }
        atomicAdd(&g_qn[b*64 + tid], s);
    } else if (tid < 128) {
        int ch = tid - 64;
        float s = 0.f;
#pragma unroll 8
        for (int px = 0; px < 64; px++) {
            float v = __uint_as_float(S[FKT + px*SP + ch]); s += v*v;
        }
        atomicAdd(&g_kn[b*64 + ch], s);
    }
}

// ---------------- apply with per-block softmax recompute --------------------
__global__ void k_applysm() {
    __shared__ __align__(16) float sa[HEADS*CH*CH];
    int tid = threadIdx.x;
    int b = blockIdx.y;
    if (tid < 64) {
        int h = tid >> 4, c = tid & 15;
        float nq = fmaxf(sqrtf(g_qn[b*CC + h*CH + c]), EPS);
        float l[16], m = -1e30f;
#pragma unroll
        for (int d = 0; d < 16; d++) {
            float nk = fmaxf(sqrtf(g_kn[b*CC + h*CH + d]), EPS);
            l[d] = g_gram[(b*4+h)*256 + c*16 + d] / (nq * nk);
            m = fmaxf(m, l[d]);
        }
        float s = 0.f;
#pragma unroll
        for (int d = 0; d < 16; d++) { l[d] = expf(l[d] - m); s += l[d]; }
        float inv = 1.f / s;
#pragma unroll
        for (int d = 0; d < 16; d++) sa[h*256 + c*16 + d] = l[d] * inv;
    }
    __syncthreads();
    int px = blockIdx.x*256 + tid;
    const float* vb = g_v  + (size_t)b*CC*HW + px;
    float*       ob = g_t0 + (size_t)b*CC*HW + px;
#pragma unroll
    for (int h = 0; h < 4; h++) {
        float vr[16];
#pragma unroll
        for (int d = 0; d < 16; d++) vr[d] = vb[(size_t)(h*CH + d)*HW];
#pragma unroll
        for (int c = 0; c < 16; c++) {
            const float4* a4 = reinterpret_cast<const float4*>(sa + h*256 + c*16);
            float s = 0.f;
#pragma unroll
            for (int d4 = 0; d4 < 4; d4++) {
                float4 a = a4[d4];
                s += a.x*vr[d4*4+0] + a.y*vr[d4*4+1] + a.z*vr[d4*4+2] + a.w*vr[d4*4+3];
            }
            ob[(size_t)(h*CH + c)*HW] = s;
        }
    }
}

// ---------------- 3x3 conv: tf32 mma + cp.async, 32x8 tile ------------------
// Block 256 = 8 warps (wm 0..3, wn 0..1). Tile 64 oc x 256 px (32w x 8h).
// Input: [8 ic][10 y][40 x] aligned window (gx0-4..gx0+35), 16B zfill copies.
// Row stride 40, ic stride 424 (=8 mod 32: conflict-free B LDS).
#define ICS 424
#define WS  72
#define INB (8*ICS)      /* 3392 u32 per input buffer  */
#define WB  (9*8*WS)     /* 5184 u32 per weight buffer */
#define SM_IN(s) ((s)*INB)
#define SM_W(s)  (2*INB + (s)*WB)
#define SMEM_U32C (2*INB + 2*WB)   /* 17152 u32 = 68608 B */

__global__ void __launch_bounds__(256, 2) k_conv3t(
        const float* __restrict__ in, const u32* __restrict__ wbuf,
        const float* __restrict__ bias, const float* __restrict__ skip,
        const float* __restrict__ skip2, float* __restrict__ out, int do_relu) {
    extern __shared__ __align__(16) u32 S[];
    int tid = threadIdx.x, lane = tid & 31, wid = tid >> 5;
    int wm = wid & 3, wn = wid >> 2;
    int t4 = lane & 3, g8 = lane >> 2;
    int b = blockIdx.z, gy0 = blockIdx.y*8, gx0 = blockIdx.x*32;
    const float* inb = in + (size_t)b*CC*HW;
    u32 sbase = smaddr(S);

    float acc[16][4];
#pragma unroll
    for (int j = 0; j < 16; j++)
#pragma unroll
        for (int r = 0; r < 4; r++) acc[j][r] = 0.f;

    auto prefetch = [&](int cc, int s) {
        int icb = cc*8;
        // input: 8 ic x 10 y x 10 segs of 16B, zfill at borders
#pragma unroll
        for (int it = 0; it < 4; it++) {
            int i = tid + it*256;
            if (i < 800) {
                int q = i / 10, seg = i - q*10;
                int ic = q / 10, yy = q - ic*10;
                int iy = gy0 + yy - 1;
                int ix0 = gx0 - 4 + seg*4;
                bool ok = (iy >= 0 && iy < HH && ix0 >= 0 && ix0 < WW);
                const float* src = ok ? (inb + (size_t)(icb+ic)*HW + iy*WW + ix0) : inb;
                cpa16z(sbase + (SM_IN(s) + ic*ICS + yy*40 + seg*4)*4, src, ok);
            }
        }
        // weights [9 tap][8 ic][oc pad 72]
#pragma unroll
        for (int it = 0; it < 5; it++) {
            int i4 = tid + it*256;
            if (i4 < 9*8*16) {
                int oc4 = i4 & 15, r = i4 >> 4;
                int ic = r & 7, tap = r >> 3;
                cpa16(sbase + (SM_W(s) + (tap*8+ic)*WS + oc4*4)*4,
                      wbuf + tap*4096 + (icb+ic)*64 + oc4*4);
            }
        }
        CP_COMMIT();
    };

    prefetch(0, 0);
    for (int c = 0; c < 8; c++) {
        int s = c & 1;
        if (c < 7) prefetch(c+1, s^1);
        if (c < 7) { CP_WAIT1(); } else { CP_WAIT0(); }
        __syncthreads();

        const u32* In = S + SM_IN(s);
        const u32* W  = S + SM_W(s);
        int base_in = t4*ICS + wn*4*40 + g8 + 3;   // py0 = wn*4
        int base_w  = t4*WS + wm*16 + g8;
#pragma unroll
        for (int tap = 0; tap < 9; tap++) {
            const int dy = tap/3, dx = tap%3;
            u32 a0 = W[base_w + tap*8*WS];
            u32 a1 = W[base_w + tap*8*WS + 8];
            u32 a2 = W[base_w + tap*8*WS + 4*WS];
            u32 a3 = W[base_w + tap*8*WS + 4*WS + 8];
            int ib = base_in + dy*40 + dx;
#pragma unroll
            for (int j = 0; j < 16; j++) {
                int off = ib + (j >> 2)*40 + (j & 3)*8;
                u32 b0 = In[off];
                u32 b1 = In[off + 4*ICS];
                mma_tf32(acc[j], a0, a1, a2, a3, b0, b1);
            }
        }
        __syncthreads();
    }

    // epilogue: j -> pixel group; p = wn*128 + j*8 + 2*t4
#pragma unroll
    for (int j = 0; j < 16; j++) {
        int p  = wn*128 + j*8 + 2*t4;
        int py = p >> 5, px = p & 31;
        size_t rowidx = (size_t)b*CC*HW + (size_t)(gy0+py)*WW + gx0 + px;
#pragma unroll
        for (int mh = 0; mh < 2; mh++) {
            int oc = wm*16 + g8 + mh*8;
            size_t idx = rowidx + (size_t)oc*HW;
            float v0 = acc[j][mh*2+0] + __ldg(&bias[oc]);
            float v1 = acc[j][mh*2+1] + __ldg(&bias[oc]);
            if (do_relu) { v0 = fmaxf(v0, 0.f); v1 = fmaxf(v1, 0.f); }
            if (skip)  { v0 += skip[idx];  v1 += skip[idx+1]; }
            if (skip2) { v0 += skip2[idx]; v1 += skip2[idx+1]; }
            *reinterpret_cast<float2*>(&out[idx]) = make_float2(v0, v1);
        }
    }
}

// ---------------- launcher ---------------------------------------------------
extern "C" void kernel_launch(void* const* d_in, const int* in_sizes, int n_in,
                              void* d_out, int out_size) {
    const float* x    = (const float*)d_in[0];
    const float* y    = (const float*)d_in[1];
    const float* qw   = (const float*)d_in[2];
    const float* qb   = (const float*)d_in[3];
    const float* kw   = (const float*)d_in[4];
    const float* kb   = (const float*)d_in[5];
    const float* vw   = (const float*)d_in[6];
    const float* vb   = (const float*)d_in[7];
    const float* r1w1 = (const float*)d_in[8];
    const float* r1b1 = (const float*)d_in[9];
    const float* r1w2 = (const float*)d_in[10];
    const float* r1b2 = (const float*)d_in[11];
    const float* r2w1 = (const float*)d_in[12];
    const float* r2b1 = (const float*)d_in[13];
    const float* r2w2 = (const float*)d_in[14];
    const float* r2b2 = (const float*)d_in[15];
    float* outp = (float*)d_out;

    float *pq, *pk, *pt0; u32* pw;
    cudaGetSymbolAddress((void**)&pq,  g_q);
    cudaGetSymbolAddress((void**)&pk,  g_k);
    cudaGetSymbolAddress((void**)&pt0, g_t0);
    cudaGetSymbolAddress((void**)&pw,  g_wbuf);

    static int smem_set = 0;
    int conv_smem  = SMEM_U32C * 4;
    int front_smem = F_TOT * 4;
    if (!smem_set) {
        cudaFuncSetAttribute(k_conv3t, cudaFuncAttributeMaxDynamicSharedMemorySize, conv_smem);
        cudaFuncSetAttribute(k_front,  cudaFuncAttributeMaxDynamicSharedMemorySize, front_smem);
        smem_set = 1;
    }

    k_wprep <<<64, 256>>>(r1w1, r1w2, r2w1, r2w2, qw, kw, vw);
    k_front <<<dim3(HW/64, BB), 256, front_smem>>>(x, y, qb, kb, vb);
    k_applysm<<<dim3(HW/256, BB), 256>>>();

    dim3 cgrid(WW/32, HH/8, BB);
    k_conv3t<<<cgrid, 256, conv_smem>>>(pt0, pw + 0*36864, r1b1, nullptr, nullptr, pq, 1);
    k_conv3t<<<cgrid, 256, conv_smem>>>(pq,  pw + 1*36864, r1b2, pt0,     nullptr, pk, 0);
    k_conv3t<<<cgrid, 256, conv_smem>>>(pk,  pw + 2*36864, r2b1, nullptr, nullptr, pq, 1);
    k_conv3t<<<cgrid, 256, conv_smem>>>(pq,  pw + 3*36864, r2b2, pk,      y,       outp, 0);
}

// round 16
// speedup vs baseline: 2.1594x; 1.0252x over previous
#include <cuda_runtime.h>
#include <cuda_bf16.h>
#include <math.h>

#define BB 8
#define CC 64
#define HEADS 4
#define CH 16
#define HH 256
#define WW 256
#define HW (HH*WW)
#define EPS 1e-12f

typedef unsigned int u32;

// ---------------- static device scratch ----------------
__device__ float g_q [BB*CC*HW];   // conv scratch
__device__ float g_k [BB*CC*HW];   // conv scratch
__device__ float g_v [BB*CC*HW];
__device__ float g_t0[BB*CC*HW];
__device__ float g_gram[BB*HEADS*CH*CH];
__device__ float g_qn[BB*CC];
__device__ float g_kn[BB*CC];
// conv weights, fragment-major: [conv][chunk8][tap][wm][lane][4]
__device__ __align__(16) u32 g_wbuf [4*9*64*64];
__device__ __align__(16) u32 g_wqkv[3*64*64];     // qkv wts [g][ic][oc] tf32

__device__ __forceinline__ u32 to_tf32(float v) {
    u32 t; asm("cvt.rna.tf32.f32 %0, %1;" : "=r"(t) : "f"(v)); return t;
}
__device__ __forceinline__ void mma_tf32(float* d, u32 a0, u32 a1, u32 a2, u32 a3,
                                         u32 b0, u32 b1) {
    asm volatile(
        "mma.sync.aligned.m16n8k8.row.col.f32.tf32.tf32.f32 "
        "{%0,%1,%2,%3}, {%4,%5,%6,%7}, {%8,%9}, {%0,%1,%2,%3};"
        : "+f"(d[0]), "+f"(d[1]), "+f"(d[2]), "+f"(d[3])
        : "r"(a0), "r"(a1), "r"(a2), "r"(a3), "r"(b0), "r"(b1));
}
__device__ __forceinline__ u32 smaddr(const void* p) {
    return (u32)__cvta_generic_to_shared(p);
}
__device__ __forceinline__ void cpa16(u32 dst, const void* src) {
    asm volatile("cp.async.cg.shared.global [%0], [%1], 16;"
                 :: "r"(dst), "l"(src) : "memory");
}
__device__ __forceinline__ void cpa16z(u32 dst, const void* src, bool ok) {
    asm volatile("cp.async.cg.shared.global [%0], [%1], 16, %2;"
                 :: "r"(dst), "l"(src), "r"(ok ? 16 : 0) : "memory");
}
#define CP_COMMIT() asm volatile("cp.async.commit_group;" ::: "memory")
#define CP_WAIT1()  asm volatile("cp.async.wait_group 1;" ::: "memory")
#define CP_WAIT0()  asm volatile("cp.async.wait_group 0;" ::: "memory")

// ---------------- weight prep + zeroing (tiny, runs first) ------------------
__global__ void k_wprep(const float* __restrict__ w0, const float* __restrict__ w1,
                        const float* __restrict__ w2, const float* __restrict__ w3,
                        const float* __restrict__ qw, const float* __restrict__ kw,
                        const float* __restrict__ vw) {
    int gtid = blockIdx.x*256 + threadIdx.x;     // 16384 threads
    const float* ws[4] = {w0, w1, w2, w3};
#pragma unroll
    for (int c = 0; c < 4; c++) {
        const float* wp = ws[c];
        for (int e = gtid; e < 9*64*64; e += 16384) {
            // fragment-major: e = chunk*4608 + ((tap*4+wm)*32+lane)*4 + comp
            int chunk = e / 4608;
            int q = e - chunk*4608;
            int comp = q & 3;
            int r4 = q >> 2;           // 0..1151
            int tap = r4 >> 7;
            int r2 = r4 & 127;
            int wm = r2 >> 5, lane = r2 & 31;
            int t4 = lane & 3, g8 = lane >> 2;
            int ic = chunk*8 + t4 + ((comp >> 1) << 2);
            int oc = wm*16 + g8 + ((comp & 1) << 3);
            g_wbuf[c*36864 + e] = to_tf32(wp[oc*576 + ic*9 + tap]);
        }
    }
    const float* qs[3] = {qw, kw, vw};
#pragma unroll
    for (int g = 0; g < 3; g++) {
        for (int e = gtid; e < 4096; e += 16384) {
            int ic = e >> 6, oc = e & 63;
            g_wqkv[g*4096 + ic*64 + oc] = to_tf32(qs[g][oc*64 + ic]);
        }
    }
    if (gtid < BB*HEADS*CH*CH) g_gram[gtid] = 0.f;
    if (gtid < BB*CC) { g_qn[gtid] = 0.f; g_kn[gtid] = 0.f; }
}

// ---------------- fused qkv + gram + norms (512 thr, 128 px) ----------------
// Warp grid: wm 0..3 (oc), wn 0..3 (32-px quarter). Weights in smem once.
#define SP2 136
#define PW 0                              /* [g][64 ic][72]: 3*4608 = 13824 */
#define PX(s) (13824 + (s)*4352)
#define PY(s) (PX(s) + 2176)
#define PFQ   22528                       /* [64 ch][136] = 8704 */
#define PFKT  31232                       /* [128 px][68] = 8704 */
#define F_TOT 39936                       /* u32 -> 159744 B */

__global__ void __launch_bounds__(512) k_front(
        const float* __restrict__ x, const float* __restrict__ y,
        const float* __restrict__ qb, const float* __restrict__ kb,
        const float* __restrict__ vb) {
    extern __shared__ __align__(16) u32 S[];
    int tid = threadIdx.x, lane = tid & 31, wid = tid >> 5;
    int wm = wid & 3, wn = wid >> 2;           // wn 0..3
    int t4 = lane & 3, g8 = lane >> 2;
    int b = blockIdx.y;
    int px0 = blockIdx.x*128;
    const float* xb = x + (size_t)b*CC*HW + px0;
    const float* yb = y + (size_t)b*CC*HW + px0;
    u32 sbase = smaddr(S);

    float aQ[4][4], aK[4][4], aV[4][4];
#pragma unroll
    for (int j = 0; j < 4; j++)
#pragma unroll
        for (int r = 0; r < 4; r++) { aQ[j][r] = 0.f; aK[j][r] = 0.f; aV[j][r] = 0.f; }

    // weights once (3072 x 16B)
#pragma unroll
    for (int it = 0; it < 6; it++) {
        int i = tid + it*512;
        int g = i >> 10, r = i & 1023;
        int ic = r >> 4, seg = r & 15;
        cpa16(sbase + (PW + g*4608 + ic*72 + seg*4)*4,
              g_wqkv + g*4096 + ic*64 + seg*4);
    }
    CP_COMMIT();

    auto prefetch = [&](int cc, int s) {
        int icb = cc*16;
#pragma unroll
        for (int it = 0; it < 2; it++) {
            int i = tid + it*512;                 // 0..1023
            int mat = i >> 9, r = i & 511;
            int ic = r >> 5, seg = r & 31;
            const float* src = (mat ? yb : xb) + (size_t)(icb+ic)*HW + seg*4;
            cpa16(sbase + ((mat ? PY(s) : PX(s)) + ic*SP2 + seg*4)*4, src);
        }
        CP_COMMIT();
    };

    prefetch(0, 0);
    for (int c = 0; c < 4; c++) {
        int s = c & 1;
        if (c < 3) prefetch(c+1, s^1);
        if (c < 3) { CP_WAIT1(); } else { CP_WAIT0(); }
        __syncthreads();
        int icb = c*16;
        const u32* X = S + PX(s);
        const u32* Y = S + PY(s);
#pragma unroll
        for (int ks = 0; ks < 2; ks++) {
            int ar = (icb + ks*8 + t4)*72 + wm*16 + g8;
            u32 qa0 = S[PW+ar],           qa1 = S[PW+ar+8];
            u32 qa2 = S[PW+ar+4*72],      qa3 = S[PW+ar+4*72+8];
            u32 ka0 = S[PW+4608+ar],      ka1 = S[PW+4608+ar+8];
            u32 ka2 = S[PW+4608+ar+4*72], ka3 = S[PW+4608+ar+4*72+8];
            u32 va0 = S[PW+9216+ar],      va1 = S[PW+9216+ar+8];
            u32 va2 = S[PW+9216+ar+4*72], va3 = S[PW+9216+ar+4*72+8];
            int ib = (ks*8 + t4)*SP2;
#pragma unroll
            for (int j = 0; j < 4; j++) {
                int px = wn*32 + j*8 + g8;
                u32 bx0 = X[ib + px], bx1 = X[ib + 4*SP2 + px];
                u32 by0 = Y[ib + px], by1 = Y[ib + 4*SP2 + px];
                mma_tf32(aQ[j], qa0, qa1, qa2, qa3, bx0, bx1);
                mma_tf32(aK[j], ka0, ka1, ka2, ka3, by0, by1);
                mma_tf32(aV[j], va0, va1, va2, va3, by0, by1);
            }
        }
        __syncthreads();
    }

    // epilogue: q -> sQ[ch][px], k -> sKT[px][ch], v -> gmem
    float* vout = g_v + (size_t)b*CC*HW + px0;
#pragma unroll
    for (int j = 0; j < 4; j++) {
        int p = wn*32 + j*8 + 2*t4;
#pragma unroll
        for (int mh = 0; mh < 2; mh++) {
            int oc = wm*16 + g8 + mh*8;
            float qv = __ldg(&qb[oc]), kv = __ldg(&kb[oc]), vv = __ldg(&vb[oc]);
            float q0 = aQ[j][mh*2+0] + qv, q1 = aQ[j][mh*2+1] + qv;
            float k0 = aK[j][mh*2+0] + kv, k1 = aK[j][mh*2+1] + kv;
            S[PFQ  + oc*SP2 + p]     = __float_as_uint(q0);
            S[PFQ  + oc*SP2 + p + 1] = __float_as_uint(q1);
            S[PFKT + p*68 + oc]      = __float_as_uint(k0);
            S[PFKT + (p+1)*68 + oc]  = __float_as_uint(k1);
            *reinterpret_cast<float2*>(&vout[(size_t)oc*HW + p]) =
                make_float2(aV[j][mh*2+0] + vv, aV[j][mh*2+1] + vv);
        }
    }
    __syncthreads();

    // gram partial: warp -> (h, nb, px-half); contract 64 px each
    {
        int h = wid & 3, nb = ((wid >> 2) & 1)*8, half = wid >> 3;
        float G[4] = {0.f, 0.f, 0.f, 0.f};
        const u32* Q  = S + PFQ;
        const u32* KT = S + PFKT;
#pragma unroll
        for (int k0 = 0; k0 < 8; k0++) {
            int ar = (h*16 + g8)*SP2 + half*64 + k0*8 + t4;
            u32 a0 = Q[ar],     a1 = Q[ar + 8*SP2];
            u32 a2 = Q[ar + 4], a3 = Q[ar + 8*SP2 + 4];
            int br = (half*64 + k0*8 + t4)*68 + h*16 + nb + g8;
            u32 b0 = KT[br], b1 = KT[br + 4*68];
            mma_tf32(G, a0, a1, a2, a3, b0, b1);
        }
        float* gg = &g_gram[((size_t)b*4 + h)*256];
        atomicAdd(&gg[(g8)*16   + nb + 2*t4],     G[0]);
        atomicAdd(&gg[(g8)*16   + nb + 2*t4 + 1], G[1]);
        atomicAdd(&gg[(g8+8)*16 + nb + 2*t4],     G[2]);
        atomicAdd(&gg[(g8+8)*16 + nb + 2*t4 + 1], G[3]);
    }
    // norm partials (128 px per channel)
    if (tid < 64) {
        float s = 0.f;
#pragma unroll 8
        for (int px = 0; px < 128; px++) {
            float v = __uint_as_float(S[PFQ + tid*SP2 + px]); s += v*v;
        }
        atomicAdd(&g_qn[b*64 + tid], s);
    } else if (tid < 128) {
        int ch = tid - 64;
        float s = 0.f;
#pragma unroll 8
        for (int px = 0; px < 128; px++) {
            float v = __uint_as_float(S[PFKT + px*68 + ch]); s += v*v;
        }
        atomicAdd(&g_kn[b*64 + ch], s);
    }
}

// ---------------- apply with per-block softmax recompute --------------------
__global__ void k_applysm() {
    __shared__ __align__(16) float sa[HEADS*CH*CH];
    int tid = threadIdx.x;
    int b = blockIdx.y;
    if (tid < 64) {
        int h = tid >> 4, c = tid & 15;
        float nq = fmaxf(sqrtf(g_qn[b*CC + h*CH + c]), EPS);
        float l[16], m = -1e30f;
#pragma unroll
        for (int d = 0; d < 16; d++) {
            float nk = fmaxf(sqrtf(g_kn[b*CC + h*CH + d]), EPS);
            l[d] = g_gram[(b*4+h)*256 + c*16 + d] / (nq * nk);
            m = fmaxf(m, l[d]);
        }
        float s = 0.f;
#pragma unroll
        for (int d = 0; d < 16; d++) { l[d] = expf(l[d] - m); s += l[d]; }
        float inv = 1.f / s;
#pragma unroll
        for (int d = 0; d < 16; d++) sa[h*256 + c*16 + d] = l[d] * inv;
    }
    __syncthreads();
    int px = blockIdx.x*256 + tid;
    const float* vb = g_v  + (size_t)b*CC*HW + px;
    float*       ob = g_t0 + (size_t)b*CC*HW + px;
#pragma unroll
    for (int h = 0; h < 4; h++) {
        float vr[16];
#pragma unroll
        for (int d = 0; d < 16; d++) vr[d] = vb[(size_t)(h*CH + d)*HW];
#pragma unroll
        for (int c = 0; c < 16; c++) {
            const float4* a4 = reinterpret_cast<const float4*>(sa + h*256 + c*16);
            float s = 0.f;
#pragma unroll
            for (int d4 = 0; d4 < 4; d4++) {
                float4 a = a4[d4];
                s += a.x*vr[d4*4+0] + a.y*vr[d4*4+1] + a.z*vr[d4*4+2] + a.w*vr[d4*4+3];
            }
            ob[(size_t)(h*CH + c)*HW] = s;
        }
    }
}

// ---------------- 3x3 conv: tf32 mma, 3-stage cp.async, vector A-frags ------
// Block 256 = 8 warps (wm 0..3, wn 0..1). Tile 64 oc x 256 px (32w x 8h).
// Input [8 ic][10 y][40 x]; weights fragment-major [tap][wm][lane][4].
#define ICS 424
#define INB 3392                 /* input u32 per stage */
#define WB2 4608                 /* weight u32 per stage */
#define STG (INB + WB2)          /* 8000 u32 = 32 KB */
#define SMEM_U32C (3*STG)        /* 24000 u32 = 96000 B */

__global__ void __launch_bounds__(256, 2) k_conv3t(
        const float* __restrict__ in, const u32* __restrict__ wbuf,
        const float* __restrict__ bias, const float* __restrict__ skip,
        const float* __restrict__ skip2, float* __restrict__ out, int do_relu) {
    extern __shared__ __align__(16) u32 S[];
    int tid = threadIdx.x, lane = tid & 31, wid = tid >> 5;
    int wm = wid & 3, wn = wid >> 2;
    int t4 = lane & 3, g8 = lane >> 2;
    int b = blockIdx.z, gy0 = blockIdx.y*8, gx0 = blockIdx.x*32;
    const float* inb = in + (size_t)b*CC*HW;
    u32 sbase = smaddr(S);

    float acc[16][4];
#pragma unroll
    for (int j = 0; j < 16; j++)
#pragma unroll
        for (int r = 0; r < 4; r++) acc[j][r] = 0.f;

    auto prefetch = [&](int cc, int s) {
        int icb = cc*8;
#pragma unroll
        for (int it = 0; it < 4; it++) {
            int i = tid + it*256;
            if (i < 800) {
                int q = i / 10, seg = i - q*10;
                int ic = q / 10, yy = q - ic*10;
                int iy = gy0 + yy - 1;
                int ix0 = gx0 - 4 + seg*4;
                bool ok = (iy >= 0 && iy < HH && ix0 >= 0 && ix0 < WW);
                const float* src = ok ? (inb + (size_t)(icb+ic)*HW + iy*WW + ix0) : inb;
                cpa16z(sbase + (s*STG + ic*ICS + yy*40 + seg*4)*4, src, ok);
            }
        }
#pragma unroll
        for (int it = 0; it < 5; it++) {
            int i4 = tid + it*256;
            if (i4 < 1152) {
                cpa16(sbase + (s*STG + INB + i4*4)*4, wbuf + cc*WB2 + i4*4);
            }
        }
        CP_COMMIT();
    };

    prefetch(0, 0);
    prefetch(1, 1);
    for (int c = 0; c < 8; c++) {
        if (c < 7) { CP_WAIT1(); } else { CP_WAIT0(); }
        __syncthreads();
        if (c < 6) prefetch(c+2, (c+2) % 3);

        int s = c % 3;
        const u32* In = S + s*STG;
        const uint4* W4 = reinterpret_cast<const uint4*>(S + s*STG + INB);
        int base_in = t4*ICS + wn*4*40 + g8 + 3;
        int base_w4 = wm*32 + lane;
#pragma unroll
        for (int tap = 0; tap < 9; tap++) {
            const int dy = tap/3, dx = tap%3;
            uint4 wv = W4[tap*128 + base_w4];
            int ib = base_in + dy*40 + dx;
#pragma unroll
            for (int j = 0; j < 16; j++) {
                int off = ib + (j >> 2)*40 + (j & 3)*8;
                u32 b0 = In[off];
                u32 b1 = In[off + 4*ICS];
                mma_tf32(acc[j], wv.x, wv.y, wv.z, wv.w, b0, b1);
            }
        }
    }

    // epilogue
#pragma unroll
    for (int j = 0; j < 16; j++) {
        int p  = wn*128 + j*8 + 2*t4;
        int py = p >> 5, px = p & 31;
        size_t rowidx = (size_t)b*CC*HW + (size_t)(gy0+py)*WW + gx0 + px;
#pragma unroll
        for (int mh = 0; mh < 2; mh++) {
            int oc = wm*16 + g8 + mh*8;
            size_t idx = rowidx + (size_t)oc*HW;
            float v0 = acc[j][mh*2+0] + __ldg(&bias[oc]);
            float v1 = acc[j][mh*2+1] + __ldg(&bias[oc]);
            if (do_relu) { v0 = fmaxf(v0, 0.f); v1 = fmaxf(v1, 0.f); }
            if (skip)  { v0 += skip[idx];  v1 += skip[idx+1]; }
            if (skip2) { v0 += skip2[idx]; v1 += skip2[idx+1]; }
            *reinterpret_cast<float2*>(&out[idx]) = make_float2(v0, v1);
        }
    }
}

// ---------------- launcher ---------------------------------------------------
extern "C" void kernel_launch(void* const* d_in, const int* in_sizes, int n_in,
                              void* d_out, int out_size) {
    const float* x    = (const float*)d_in[0];
    const float* y    = (const float*)d_in[1];
    const float* qw   = (const float*)d_in[2];
    const float* qb   = (const float*)d_in[3];
    const float* kw   = (const float*)d_in[4];
    const float* kb   = (const float*)d_in[5];
    const float* vw   = (const float*)d_in[6];
    const float* vb   = (const float*)d_in[7];
    const float* r1w1 = (const float*)d_in[8];
    const float* r1b1 = (const float*)d_in[9];
    const float* r1w2 = (const float*)d_in[10];
    const float* r1b2 = (const float*)d_in[11];
    const float* r2w1 = (const float*)d_in[12];
    const float* r2b1 = (const float*)d_in[13];
    const float* r2w2 = (const float*)d_in[14];
    const float* r2b2 = (const float*)d_in[15];
    float* outp = (float*)d_out;

    float *pq, *pk, *pt0; u32* pw;
    cudaGetSymbolAddress((void**)&pq,  g_q);
    cudaGetSymbolAddress((void**)&pk,  g_k);
    cudaGetSymbolAddress((void**)&pt0, g_t0);
    cudaGetSymbolAddress((void**)&pw,  g_wbuf);

    static int smem_set = 0;
    int conv_smem  = SMEM_U32C * 4;
    int front_smem = F_TOT * 4;
    if (!smem_set) {
        cudaFuncSetAttribute(k_conv3t, cudaFuncAttributeMaxDynamicSharedMemorySize, conv_smem);
        cudaFuncSetAttribute(k_front,  cudaFuncAttributeMaxDynamicSharedMemorySize, front_smem);
        smem_set = 1;
    }

    k_wprep <<<64, 256>>>(r1w1, r1w2, r2w1, r2w2, qw, kw, vw);
    k_front <<<dim3(HW/128, BB), 512, front_smem>>>(x, y, qb, kb, vb);
    k_applysm<<<dim3(HW/256, BB), 256>>>();

    dim3 cgrid(WW/32, HH/8, BB);
    k_conv3t<<<cgrid, 256, conv_smem>>>(pt0, pw + 0*36864, r1b1, nullptr, nullptr, pq, 1);
    k_conv3t<<<cgrid, 256, conv_smem>>>(pq,  pw + 1*36864, r1b2, pt0,     nullptr, pk, 0);
    k_conv3t<<<cgrid, 256, conv_smem>>>(pk,  pw + 2*36864, r2b1, nullptr, nullptr, pq, 1);
    k_conv3t<<<cgrid, 256, conv_smem>>>(pq,  pw + 3*36864, r2b2, pk,      y,       outp, 0);
}

// round 17
// speedup vs baseline: 2.2230x; 1.0295x over previous
#include <cuda_runtime.h>
#include <cuda_bf16.h>
#include <math.h>

#define BB 8
#define CC 64
#define HEADS 4
#define CH 16
#define HH 256
#define WW 256
#define HW (HH*WW)
#define EPS 1e-12f

typedef unsigned int u32;

// ---------------- static device scratch ----------------
__device__ float g_q [BB*CC*HW];   // conv scratch
__device__ float g_k [BB*CC*HW];   // conv scratch
__device__ float g_v [BB*CC*HW];
__device__ float g_t0[BB*CC*HW];
__device__ float g_gram[BB*HEADS*CH*CH];
__device__ float g_qn[BB*CC];
__device__ float g_kn[BB*CC];
// conv weights, fragment-major: [conv][chunk8][tap][ocg][lane][4]
__device__ __align__(16) u32 g_wbuf [4*9*64*64];
__device__ __align__(16) u32 g_wqkv[3*64*64];     // qkv wts [g][ic][oc] tf32

__device__ __forceinline__ u32 to_tf32(float v) {
    u32 t; asm("cvt.rna.tf32.f32 %0, %1;" : "=r"(t) : "f"(v)); return t;
}
__device__ __forceinline__ void mma_tf32(float* d, u32 a0, u32 a1, u32 a2, u32 a3,
                                         u32 b0, u32 b1) {
    asm volatile(
        "mma.sync.aligned.m16n8k8.row.col.f32.tf32.tf32.f32 "
        "{%0,%1,%2,%3}, {%4,%5,%6,%7}, {%8,%9}, {%0,%1,%2,%3};"
        : "+f"(d[0]), "+f"(d[1]), "+f"(d[2]), "+f"(d[3])
        : "r"(a0), "r"(a1), "r"(a2), "r"(a3), "r"(b0), "r"(b1));
}
__device__ __forceinline__ u32 smaddr(const void* p) {
    return (u32)__cvta_generic_to_shared(p);
}
__device__ __forceinline__ void cpa16(u32 dst, const void* src) {
    asm volatile("cp.async.cg.shared.global [%0], [%1], 16;"
                 :: "r"(dst), "l"(src) : "memory");
}
__device__ __forceinline__ void cpa16z(u32 dst, const void* src, bool ok) {
    asm volatile("cp.async.cg.shared.global [%0], [%1], 16, %2;"
                 :: "r"(dst), "l"(src), "r"(ok ? 16 : 0) : "memory");
}
#define CP_COMMIT() asm volatile("cp.async.commit_group;" ::: "memory")
#define CP_WAIT1()  asm volatile("cp.async.wait_group 1;" ::: "memory")
#define CP_WAIT0()  asm volatile("cp.async.wait_group 0;" ::: "memory")

// ---------------- weight prep + zeroing (tiny, runs first) ------------------
__global__ void k_wprep(const float* __restrict__ w0, const float* __restrict__ w1,
                        const float* __restrict__ w2, const float* __restrict__ w3,
                        const float* __restrict__ qw, const float* __restrict__ kw,
                        const float* __restrict__ vw) {
    int gtid = blockIdx.x*256 + threadIdx.x;     // 16384 threads
    const float* ws[4] = {w0, w1, w2, w3};
#pragma unroll
    for (int c = 0; c < 4; c++) {
        const float* wp = ws[c];
        for (int e = gtid; e < 9*64*64; e += 16384) {
            // fragment-major: e = chunk*4608 + ((tap*4+ocg)*32+lane)*4 + comp
            int chunk = e / 4608;
            int q = e - chunk*4608;
            int comp = q & 3;
            int r4 = q >> 2;           // 0..1151
            int tap = r4 >> 7;
            int r2 = r4 & 127;
            int ocg = r2 >> 5, lane = r2 & 31;
            int t4 = lane & 3, g8 = lane >> 2;
            int ic = chunk*8 + t4 + ((comp >> 1) << 2);
            int oc = ocg*16 + g8 + ((comp & 1) << 3);
            g_wbuf[c*36864 + e] = to_tf32(wp[oc*576 + ic*9 + tap]);
        }
    }
    const float* qs[3] = {qw, kw, vw};
#pragma unroll
    for (int g = 0; g < 3; g++) {
        for (int e = gtid; e < 4096; e += 16384) {
            int ic = e >> 6, oc = e & 63;
            g_wqkv[g*4096 + ic*64 + oc] = to_tf32(qs[g][oc*64 + ic]);
        }
    }
    if (gtid < BB*HEADS*CH*CH) g_gram[gtid] = 0.f;
    if (gtid < BB*CC) { g_qn[gtid] = 0.f; g_kn[gtid] = 0.f; }
}

// ---------------- fused qkv + gram + norms (512 thr, 128 px) ----------------
#define SP2 136
#define PW 0                              /* [g][64 ic][72]: 3*4608 = 13824 */
#define PX(s) (13824 + (s)*4352)
#define PY(s) (PX(s) + 2176)
#define PFQ   22528                       /* [64 ch][136] = 8704 */
#define PFKT  31232                       /* [128 px][68] = 8704 */
#define F_TOT 39936                       /* u32 -> 159744 B */

__global__ void __launch_bounds__(512) k_front(
        const float* __restrict__ x, const float* __restrict__ y,
        const float* __restrict__ qb, const float* __restrict__ kb,
        const float* __restrict__ vb) {
    extern __shared__ __align__(16) u32 S[];
    int tid = threadIdx.x, lane = tid & 31, wid = tid >> 5;
    int wm = wid & 3, wn = wid >> 2;           // wn 0..3
    int t4 = lane & 3, g8 = lane >> 2;
    int b = blockIdx.y;
    int px0 = blockIdx.x*128;
    const float* xb = x + (size_t)b*CC*HW + px0;
    const float* yb = y + (size_t)b*CC*HW + px0;
    u32 sbase = smaddr(S);

    float aQ[4][4], aK[4][4], aV[4][4];
#pragma unroll
    for (int j = 0; j < 4; j++)
#pragma unroll
        for (int r = 0; r < 4; r++) { aQ[j][r] = 0.f; aK[j][r] = 0.f; aV[j][r] = 0.f; }

    // weights once (3072 x 16B)
#pragma unroll
    for (int it = 0; it < 6; it++) {
        int i = tid + it*512;
        int g = i >> 10, r = i & 1023;
        int ic = r >> 4, seg = r & 15;
        cpa16(sbase + (PW + g*4608 + ic*72 + seg*4)*4,
              g_wqkv + g*4096 + ic*64 + seg*4);
    }
    CP_COMMIT();

    auto prefetch = [&](int cc, int s) {
        int icb = cc*16;
#pragma unroll
        for (int it = 0; it < 2; it++) {
            int i = tid + it*512;                 // 0..1023
            int mat = i >> 9, r = i & 511;
            int ic = r >> 5, seg = r & 31;
            const float* src = (mat ? yb : xb) + (size_t)(icb+ic)*HW + seg*4;
            cpa16(sbase + ((mat ? PY(s) : PX(s)) + ic*SP2 + seg*4)*4, src);
        }
        CP_COMMIT();
    };

    prefetch(0, 0);
    for (int c = 0; c < 4; c++) {
        int s = c & 1;
        if (c < 3) prefetch(c+1, s^1);
        if (c < 3) { CP_WAIT1(); } else { CP_WAIT0(); }
        __syncthreads();
        int icb = c*16;
        const u32* X = S + PX(s);
        const u32* Y = S + PY(s);
#pragma unroll
        for (int ks = 0; ks < 2; ks++) {
            int ar = (icb + ks*8 + t4)*72 + wm*16 + g8;
            u32 qa0 = S[PW+ar],           qa1 = S[PW+ar+8];
            u32 qa2 = S[PW+ar+4*72],      qa3 = S[PW+ar+4*72+8];
            u32 ka0 = S[PW+4608+ar],      ka1 = S[PW+4608+ar+8];
            u32 ka2 = S[PW+4608+ar+4*72], ka3 = S[PW+4608+ar+4*72+8];
            u32 va0 = S[PW+9216+ar],      va1 = S[PW+9216+ar+8];
            u32 va2 = S[PW+9216+ar+4*72], va3 = S[PW+9216+ar+4*72+8];
            int ib = (ks*8 + t4)*SP2;
#pragma unroll
            for (int j = 0; j < 4; j++) {
                int px = wn*32 + j*8 + g8;
                u32 bx0 = X[ib + px], bx1 = X[ib + 4*SP2 + px];
                u32 by0 = Y[ib + px], by1 = Y[ib + 4*SP2 + px];
                mma_tf32(aQ[j], qa0, qa1, qa2, qa3, bx0, bx1);
                mma_tf32(aK[j], ka0, ka1, ka2, ka3, by0, by1);
                mma_tf32(aV[j], va0, va1, va2, va3, by0, by1);
            }
        }
        __syncthreads();
    }

    // epilogue: q -> sQ[ch][px], k -> sKT[px][ch], v -> gmem
    float* vout = g_v + (size_t)b*CC*HW + px0;
#pragma unroll
    for (int j = 0; j < 4; j++) {
        int p = wn*32 + j*8 + 2*t4;
#pragma unroll
        for (int mh = 0; mh < 2; mh++) {
            int oc = wm*16 + g8 + mh*8;
            float qv = __ldg(&qb[oc]), kv = __ldg(&kb[oc]), vv = __ldg(&vb[oc]);
            float q0 = aQ[j][mh*2+0] + qv, q1 = aQ[j][mh*2+1] + qv;
            float k0 = aK[j][mh*2+0] + kv, k1 = aK[j][mh*2+1] + kv;
            S[PFQ  + oc*SP2 + p]     = __float_as_uint(q0);
            S[PFQ  + oc*SP2 + p + 1] = __float_as_uint(q1);
            S[PFKT + p*68 + oc]      = __float_as_uint(k0);
            S[PFKT + (p+1)*68 + oc]  = __float_as_uint(k1);
            *reinterpret_cast<float2*>(&vout[(size_t)oc*HW + p]) =
                make_float2(aV[j][mh*2+0] + vv, aV[j][mh*2+1] + vv);
        }
    }
    __syncthreads();

    // gram partial: warp -> (h, nb, px-half); contract 64 px each
    {
        int h = wid & 3, nb = ((wid >> 2) & 1)*8, half = wid >> 3;
        float G[4] = {0.f, 0.f, 0.f, 0.f};
        const u32* Q  = S + PFQ;
        const u32* KT = S + PFKT;
#pragma unroll
        for (int k0 = 0; k0 < 8; k0++) {
            int ar = (h*16 + g8)*SP2 + half*64 + k0*8 + t4;
            u32 a0 = Q[ar],     a1 = Q[ar + 8*SP2];
            u32 a2 = Q[ar + 4], a3 = Q[ar + 8*SP2 + 4];
            int br = (half*64 + k0*8 + t4)*68 + h*16 + nb + g8;
            u32 b0 = KT[br], b1 = KT[br + 4*68];
            mma_tf32(G, a0, a1, a2, a3, b0, b1);
        }
        float* gg = &g_gram[((size_t)b*4 + h)*256];
        atomicAdd(&gg[(g8)*16   + nb + 2*t4],     G[0]);
        atomicAdd(&gg[(g8)*16   + nb + 2*t4 + 1], G[1]);
        atomicAdd(&gg[(g8+8)*16 + nb + 2*t4],     G[2]);
        atomicAdd(&gg[(g8+8)*16 + nb + 2*t4 + 1], G[3]);
    }
    // norm partials (128 px per channel)
    if (tid < 64) {
        float s = 0.f;
#pragma unroll 8
        for (int px = 0; px < 128; px++) {
            float v = __uint_as_float(S[PFQ + tid*SP2 + px]); s += v*v;
        }
        atomicAdd(&g_qn[b*64 + tid], s);
    } else if (tid < 128) {
        int ch = tid - 64;
        float s = 0.f;
#pragma unroll 8
        for (int px = 0; px < 128; px++) {
            float v = __uint_as_float(S[PFKT + px*68 + ch]); s += v*v;
        }
        atomicAdd(&g_kn[b*64 + ch], s);
    }
}

// ---------------- apply with per-block softmax recompute --------------------
__global__ void k_applysm() {
    __shared__ __align__(16) float sa[HEADS*CH*CH];
    int tid = threadIdx.x;
    int b = blockIdx.y;
    if (tid < 64) {
        int h = tid >> 4, c = tid & 15;
        float nq = fmaxf(sqrtf(g_qn[b*CC + h*CH + c]), EPS);
        float l[16], m = -1e30f;
#pragma unroll
        for (int d = 0; d < 16; d++) {
            float nk = fmaxf(sqrtf(g_kn[b*CC + h*CH + d]), EPS);
            l[d] = g_gram[(b*4+h)*256 + c*16 + d] / (nq * nk);
            m = fmaxf(m, l[d]);
        }
        float s = 0.f;
#pragma unroll
        for (int d = 0; d < 16; d++) { l[d] = expf(l[d] - m); s += l[d]; }
        float inv = 1.f / s;
#pragma unroll
        for (int d = 0; d < 16; d++) sa[h*256 + c*16 + d] = l[d] * inv;
    }
    __syncthreads();
    int px = blockIdx.x*256 + tid;
    const float* vb = g_v  + (size_t)b*CC*HW + px;
    float*       ob = g_t0 + (size_t)b*CC*HW + px;
#pragma unroll
    for (int h = 0; h < 4; h++) {
        float vr[16];
#pragma unroll
        for (int d = 0; d < 16; d++) vr[d] = vb[(size_t)(h*CH + d)*HW];
#pragma unroll
        for (int c = 0; c < 16; c++) {
            const float4* a4 = reinterpret_cast<const float4*>(sa + h*256 + c*16);
            float s = 0.f;
#pragma unroll
            for (int d4 = 0; d4 < 4; d4++) {
                float4 a = a4[d4];
                s += a.x*vr[d4*4+0] + a.y*vr[d4*4+1] + a.z*vr[d4*4+2] + a.w*vr[d4*4+3];
            }
            ob[(size_t)(h*CH + c)*HW] = s;
        }
    }
}

// ---------------- 3x3 conv: tf32 mma, 3-stage cp.async ----------------------
// Block 256 = 8 warps. Warp wp owns pixel row py=wp (32 px = 4 pxg) x ALL 4
// oc-groups: B-fragments loaded once per pxg (8 LDS/tap), reused across ocg;
// A-fragments 4 x LDS.128 per tap. Tile 64 oc x 256 px (32w x 8h).
#define ICS 424
#define INB 3392                 /* input u32 per stage */
#define WB2 4608                 /* weight u32 per stage */
#define STG (INB + WB2)          /* 8000 u32 = 32 KB */
#define SMEM_U32C (3*STG)        /* 24000 u32 = 96000 B */

__global__ void __launch_bounds__(256, 2) k_conv3t(
        const float* __restrict__ in, const u32* __restrict__ wbuf,
        const float* __restrict__ bias, const float* __restrict__ skip,
        const float* __restrict__ skip2, float* __restrict__ out, int do_relu) {
    extern __shared__ __align__(16) u32 S[];
    int tid = threadIdx.x, lane = tid & 31, wp = tid >> 5;
    int t4 = lane & 3, g8 = lane >> 2;
    int b = blockIdx.z, gy0 = blockIdx.y*8, gx0 = blockIdx.x*32;
    const float* inb = in + (size_t)b*CC*HW;
    u32 sbase = smaddr(S);

    float acc[16][4];                    // [jj*4 + ocg][reg]
#pragma unroll
    for (int j = 0; j < 16; j++)
#pragma unroll
        for (int r = 0; r < 4; r++) acc[j][r] = 0.f;

    auto prefetch = [&](int cc, int s) {
        int icb = cc*8;
#pragma unroll
        for (int it = 0; it < 4; it++) {
            int i = tid + it*256;
            if (i < 800) {
                int q = i / 10, seg = i - q*10;
                int ic = q / 10, yy = q - ic*10;
                int iy = gy0 + yy - 1;
                int ix0 = gx0 - 4 + seg*4;
                bool ok = (iy >= 0 && iy < HH && ix0 >= 0 && ix0 < WW);
                const float* src = ok ? (inb + (size_t)(icb+ic)*HW + iy*WW + ix0) : inb;
                cpa16z(sbase + (s*STG + ic*ICS + yy*40 + seg*4)*4, src, ok);
            }
        }
#pragma unroll
        for (int it = 0; it < 5; it++) {
            int i4 = tid + it*256;
            if (i4 < 1152) {
                cpa16(sbase + (s*STG + INB + i4*4)*4, wbuf + cc*WB2 + i4*4);
            }
        }
        CP_COMMIT();
    };

    prefetch(0, 0);
    prefetch(1, 1);
    for (int c = 0; c < 8; c++) {
        if (c < 7) { CP_WAIT1(); } else { CP_WAIT0(); }
        __syncthreads();
        if (c < 6) prefetch(c+2, (c+2) % 3);

        int s = c % 3;
        const u32* In = S + s*STG;
        const uint4* W4 = reinterpret_cast<const uint4*>(S + s*STG + INB);
#pragma unroll
        for (int tap = 0; tap < 9; tap++) {
            const int dy = tap/3, dx = tap%3;
            uint4 wv0 = W4[tap*128 + 0*32 + lane];
            uint4 wv1 = W4[tap*128 + 1*32 + lane];
            uint4 wv2 = W4[tap*128 + 2*32 + lane];
            uint4 wv3 = W4[tap*128 + 3*32 + lane];
            int ib = t4*ICS + (wp + dy)*40 + g8 + 3 + dx;
#pragma unroll
            for (int jj = 0; jj < 4; jj++) {
                u32 b0 = In[ib + jj*8];
                u32 b1 = In[ib + jj*8 + 4*ICS];
                mma_tf32(acc[jj*4+0], wv0.x, wv0.y, wv0.z, wv0.w, b0, b1);
                mma_tf32(acc[jj*4+1], wv1.x, wv1.y, wv1.z, wv1.w, b0, b1);
                mma_tf32(acc[jj*4+2], wv2.x, wv2.y, wv2.z, wv2.w, b0, b1);
                mma_tf32(acc[jj*4+3], wv3.x, wv3.y, wv3.z, wv3.w, b0, b1);
            }
        }
    }

    // epilogue: warp wp = row gy0+wp; columns jj*8 + 2*t4
#pragma unroll
    for (int jj = 0; jj < 4; jj++) {
        size_t rowidx = (size_t)b*CC*HW + (size_t)(gy0+wp)*WW + gx0 + jj*8 + 2*t4;
#pragma unroll
        for (int ocg = 0; ocg < 4; ocg++) {
#pragma unroll
            for (int mh = 0; mh < 2; mh++) {
                int oc = ocg*16 + g8 + mh*8;
                size_t idx = rowidx + (size_t)oc*HW;
                float v0 = acc[jj*4+ocg][mh*2+0] + __ldg(&bias[oc]);
                float v1 = acc[jj*4+ocg][mh*2+1] + __ldg(&bias[oc]);
                if (do_relu) { v0 = fmaxf(v0, 0.f); v1 = fmaxf(v1, 0.f); }
                if (skip)  { v0 += skip[idx];  v1 += skip[idx+1]; }
                if (skip2) { v0 += skip2[idx]; v1 += skip2[idx+1]; }
                *reinterpret_cast<float2*>(&out[idx]) = make_float2(v0, v1);
            }
        }
    }
}

// ---------------- launcher ---------------------------------------------------
extern "C" void kernel_launch(void* const* d_in, const int* in_sizes, int n_in,
                              void* d_out, int out_size) {
    const float* x    = (const float*)d_in[0];
    const float* y    = (const float*)d_in[1];
    const float* qw   = (const float*)d_in[2];
    const float* qb   = (const float*)d_in[3];
    const float* kw   = (const float*)d_in[4];
    const float* kb   = (const float*)d_in[5];
    const float* vw   = (const float*)d_in[6];
    const float* vb   = (const float*)d_in[7];
    const float* r1w1 = (const float*)d_in[8];
    const float* r1b1 = (const float*)d_in[9];
    const float* r1w2 = (const float*)d_in[10];
    const float* r1b2 = (const float*)d_in[11];
    const float* r2w1 = (const float*)d_in[12];
    const float* r2b1 = (const float*)d_in[13];
    const float* r2w2 = (const float*)d_in[14];
    const float* r2b2 = (const float*)d_in[15];
    float* outp = (float*)d_out;

    float *pq, *pk, *pt0; u32* pw;
    cudaGetSymbolAddress((void**)&pq,  g_q);
    cudaGetSymbolAddress((void**)&pk,  g_k);
    cudaGetSymbolAddress((void**)&pt0, g_t0);
    cudaGetSymbolAddress((void**)&pw,  g_wbuf);

    static int smem_set = 0;
    int conv_smem  = SMEM_U32C * 4;
    int front_smem = F_TOT * 4;
    if (!smem_set) {
        cudaFuncSetAttribute(k_conv3t, cudaFuncAttributeMaxDynamicSharedMemorySize, conv_smem);
        cudaFuncSetAttribute(k_front,  cudaFuncAttributeMaxDynamicSharedMemorySize, front_smem);
        smem_set = 1;
    }

    k_wprep <<<64, 256>>>(r1w1, r1w2, r2w1, r2w2, qw, kw, vw);
    k_front <<<dim3(HW/128, BB), 512, front_smem>>>(x, y, qb, kb, vb);
    k_applysm<<<dim3(HW/256, BB), 256>>>();

    dim3 cgrid(WW/32, HH/8, BB);
    k_conv3t<<<cgrid, 256, conv_smem>>>(pt0, pw + 0*36864, r1b1, nullptr, nullptr, pq, 1);
    k_conv3t<<<cgrid, 256, conv_smem>>>(pq,  pw + 1*36864, r1b2, pt0,     nullptr, pk, 0);
    k_conv3t<<<cgrid, 256, conv_smem>>>(pk,  pw + 2*36864, r2b1, nullptr, nullptr, pq, 1);
    k_conv3t<<<cgrid, 256, conv_smem>>>(pq,  pw + 3*36864, r2b2, pk,      y,       outp, 0);
}